// round 12
// baseline (speedup 1.0000x reference)
#include <cuda_runtime.h>
#include <cuda_bf16.h>
#include <cuda_fp16.h>
#include <math.h>
#include <stdint.h>

#define Bq 2
#define Nq 2048
#define Dq 512
#define Hq 8
#define Fq 2048
#define DHq 64
#define ROWS (Bq*Nq)            // 4096
#define BHq (Bq*Hq)             // 16
#define QKVS (3*Dq)             // 1536
#define QSCL 0.0901684403f      // (1/16) * log2(e)

// ---------------- scratch (static device globals) ---------------------------
__device__ float g_msgO[ROWS*Dq];
__device__ float g_h1[ROWS*Dq];
__device__ float g_ffn2[ROWS*Dq];
__device__ float g_rn[ROWS];

__device__ __half g_QKVh[(size_t)ROWS*QKVS];
__device__ __half g_h16[ROWS*Dq];
__device__ __half g_mh[ROWS*Dq];
__device__ __half g_h1h[ROWS*Dq];
__device__ __half g_ffn1h[(size_t)ROWS*Fq];
__device__ __half g_WqkvT[3*Dq*Dq];
__device__ __half g_WoT[Dq*Dq];
__device__ __half g_W1T[(size_t)Fq*Dq];
__device__ __half g_W2T[(size_t)Dq*Fq];
__device__ __half g_cph16[BHq*Nq];
__device__ __half g_sph16[BHq*Nq];
__device__ __half g_mask16[Bq*Nq];

// ---------------- PTX helpers -----------------------------------------------
__device__ __forceinline__ uint32_t smem_u32(const void* p) {
    return (uint32_t)__cvta_generic_to_shared(p);
}
__device__ __forceinline__ void cp16(uint32_t s, const void* g) {
    asm volatile("cp.async.cg.shared.global [%0], [%1], 16;" :: "r"(s), "l"(g));
}
__device__ __forceinline__ void cp_commit() { asm volatile("cp.async.commit_group;" ::: "memory"); }
__device__ __forceinline__ void cp_wait1()  { asm volatile("cp.async.wait_group 1;" ::: "memory"); }

__device__ __forceinline__ void ldm_x4(uint32_t* r, uint32_t addr) {
    asm volatile("ldmatrix.sync.aligned.m8n8.x4.shared.b16 {%0,%1,%2,%3}, [%4];"
                 : "=r"(r[0]), "=r"(r[1]), "=r"(r[2]), "=r"(r[3]) : "r"(addr));
}
__device__ __forceinline__ void ldm_x4_t(uint32_t* r, uint32_t addr) {
    asm volatile("ldmatrix.sync.aligned.m8n8.x4.trans.shared.b16 {%0,%1,%2,%3}, [%4];"
                 : "=r"(r[0]), "=r"(r[1]), "=r"(r[2]), "=r"(r[3]) : "r"(addr));
}
__device__ __forceinline__ void mma16816h(float* c, const uint32_t* a, const uint32_t* b) {
    asm volatile("mma.sync.aligned.m16n8k16.row.col.f32.f16.f16.f32 "
                 "{%0,%1,%2,%3}, {%4,%5,%6,%7}, {%8,%9}, {%0,%1,%2,%3};"
                 : "+f"(c[0]), "+f"(c[1]), "+f"(c[2]), "+f"(c[3])
                 : "r"(a[0]), "r"(a[1]), "r"(a[2]), "r"(a[3]), "r"(b[0]), "r"(b[1]));
}
__device__ __forceinline__ void mma16816hh(uint32_t* c, const uint32_t* a, const uint32_t* b) {
    asm volatile("mma.sync.aligned.m16n8k16.row.col.f16.f16.f16.f16 "
                 "{%0,%1}, {%2,%3,%4,%5}, {%6,%7}, {%0,%1};"
                 : "+r"(c[0]), "+r"(c[1])
                 : "r"(a[0]), "r"(a[1]), "r"(a[2]), "r"(a[3]), "r"(b[0]), "r"(b[1]));
}
__device__ __forceinline__ uint32_t ex2h2(__half2 s) {
    uint32_t r;
    asm("ex2.approx.f16x2 %0, %1;" : "=r"(r) : "r"(*(uint32_t*)&s));
    return r;
}

// ---------------- HMMA fp16 GEMM: C = A(MxK) @ BT(NxK)^T ---------------------
// epi bit0: +bias ; bit1: GELU ; bit3: fp16 out ; bit4: scale cols<Dq by QSCL
#define TSTR 40
#define TILE_B (128 * TSTR * 2)         // 10240 bytes per tile
template<int STAGES>
__global__ __launch_bounds__(256) void tgemm_kernel(
    const __half* __restrict__ A, const __half* __restrict__ B,
    const float* __restrict__ bias,
    float* __restrict__ Cf, __half* __restrict__ C16,
    int K, int Nc, int epi)
{
    extern __shared__ __align__(128) unsigned char dsm[];
    const uint32_t stg = 2 * TILE_B;
    const uint32_t sb = smem_u32(dsm);
    const int tid = threadIdx.x;
    const int warp = tid >> 5, lane = tid & 31;
    const int wm = warp >> 1, wn = warp & 1;
    const int bm = blockIdx.y * 128, bn = blockIdx.x * 128;

    const int NCH = K >> 5;
    const int lrow = tid >> 2, lch = (tid & 3) << 3;

    float acc[2][8][4];
    #pragma unroll
    for (int i = 0; i < 2; i++)
        #pragma unroll
        for (int j = 0; j < 8; j++)
            #pragma unroll
            for (int q = 0; q < 4; q++) acc[i][j][q] = 0.f;

    auto issue = [&](int c) {
        if (c < NCH) {
            const int kc = c << 5;
            const uint32_t base = sb + (uint32_t)(c % STAGES) * stg;
            #pragma unroll
            for (int i = 0; i < 2; i++) {
                const int row = lrow + i * 64;
                const uint32_t so = (uint32_t)(row * TSTR + lch) * 2;
                cp16(base + so,          A + (size_t)(bm + row) * K + kc + lch);
                cp16(base + TILE_B + so, B + (size_t)(bn + row) * K + kc + lch);
            }
        }
        cp_commit();
    };

    #pragma unroll
    for (int p = 0; p < STAGES - 1; p++) issue(p);

    for (int c = 0; c < NCH; c++) {
        asm volatile("cp.async.wait_group %0;" :: "n"(STAGES - 2));
        __syncthreads();
        issue(c + STAGES - 1);
        const uint32_t base = sb + (uint32_t)(c % STAGES) * stg;
        #pragma unroll
        for (int ks = 0; ks < 2; ks++) {
            const uint32_t arow = (uint32_t)((wm * 32 + (lane & 15)) * TSTR
                                             + ks * 16 + ((lane >> 4) << 3)) * 2;
            const uint32_t brow = (uint32_t)((wn * 64 + ((lane >> 4) << 3) + (lane & 7)) * TSTR
                                             + ks * 16 + (((lane >> 3) & 1) << 3)) * 2;
            uint32_t aH[2][4], bH[4][4];
            #pragma unroll
            for (int mt = 0; mt < 2; mt++)
                ldm_x4(aH[mt], base + arow + (uint32_t)(mt * 16 * TSTR) * 2);
            #pragma unroll
            for (int nt4 = 0; nt4 < 4; nt4++)
                ldm_x4(bH[nt4], base + TILE_B + brow + (uint32_t)(nt4 * 16 * TSTR) * 2);
            #pragma unroll
            for (int mt = 0; mt < 2; mt++)
                #pragma unroll
                for (int nt = 0; nt < 8; nt++)
                    mma16816h(acc[mt][nt], aH[mt], &bH[nt >> 1][(nt & 1) * 2]);
        }
        __syncthreads();
    }

    #pragma unroll
    for (int mt = 0; mt < 2; mt++) {
        const int r0 = bm + wm * 32 + mt * 16 + (lane >> 2);
        #pragma unroll
        for (int nt = 0; nt < 8; nt++) {
            const int gn = bn + wn * 64 + nt * 8 + ((lane & 3) << 1);
            #pragma unroll
            for (int half = 0; half < 2; half++) {
                const int row = r0 + half * 8;
                float v0 = acc[mt][nt][half * 2 + 0];
                float v1 = acc[mt][nt][half * 2 + 1];
                if (epi & 1) { v0 += bias[gn]; v1 += bias[gn + 1]; }
                if (epi & 2) {
                    v0 = 0.5f * v0 * (1.f + erff(v0 * 0.7071067811865475f));
                    v1 = 0.5f * v1 * (1.f + erff(v1 * 0.7071067811865475f));
                }
                if ((epi & 16) && gn < Dq) { v0 *= QSCL; v1 *= QSCL; }
                const size_t idx = (size_t)row * Nc + gn;
                if (epi & 8) {
                    *(__half2*)(C16 + idx) = __floats2half2_rn(v0, v1);
                } else {
                    *(float2*)(Cf + idx) = make_float2(v0, v1);
                }
            }
        }
    }
}

// ---------------- fused flash attention (fp16 acc, half2 harmonic) -----------
// Q pre-scaled by log2e/16. grid (Nq/128, BHq), 256 threads (8 warps).
#define FLASH_STAGE 37632
#define FLASH_Q     18432
#define FLASH_SMEM  (FLASH_Q + 2 * FLASH_STAGE)     // 93696
__global__ __launch_bounds__(256, 2) void flash_kernel(
    const __half* __restrict__ QKV,
    const __half* __restrict__ cph, const __half* __restrict__ sph,
    const __half* __restrict__ maskh,
    __half* __restrict__ Mh)
{
    extern __shared__ __align__(128) unsigned char fsm[];
    const int tid = threadIdx.x, warp = tid >> 5, lane = tid & 31;
    const int wq = warp & 3, wn = warp >> 2;
    const int bh = blockIdx.y, b = bh >> 3, hh = bh & 7;
    const int n0 = blockIdx.x * 128;
    const uint32_t sb = smem_u32(fsm);

    // Q tile: 128 rows x 64 cols fp16 (144B row stride)
    const __half* gQ = QKV + ((size_t)b * Nq + n0) * QKVS + hh * DHq;
    #pragma unroll
    for (int i = 0; i < 4; i++) {
        const int id = tid + i * 256, row = id >> 3, ch = id & 7;
        cp16(sb + row * 144 + ch * 16, gQ + (size_t)row * QKVS + ch * 8);
    }
    cp_commit();

    auto issueKV = [&](int step, int s) {
        const uint32_t ku = sb + FLASH_Q + s * FLASH_STAGE;
        const uint32_t vu = ku + 18432, cku = ku + 36864, sku = ku + 37120, mku = ku + 37376;
        const __half* gK = QKV + ((size_t)b * Nq + step * 128) * QKVS + Dq + hh * DHq;
        const __half* gV = gK + Dq;
        #pragma unroll
        for (int i = 0; i < 4; i++) {
            const int id = tid + i * 256, row = id >> 3, ch = id & 7;
            cp16(ku + row * 144 + ch * 16, gK + (size_t)row * QKVS + ch * 8);
            cp16(vu + row * 144 + ch * 16, gV + (size_t)row * QKVS + ch * 8);
        }
        if (tid < 16)      cp16(cku + tid * 16, cph + (size_t)bh * Nq + step * 128 + tid * 8);
        else if (tid < 32) cp16(sku + (tid - 16) * 16, sph + (size_t)bh * Nq + step * 128 + (tid - 16) * 8);
        else if (tid < 48) cp16(mku + (tid - 32) * 16, maskh + (size_t)b * Nq + step * 128 + (tid - 32) * 8);
        cp_commit();
    };
    issueKV(0, 0);
    issueKV(1, 1);
    cp_wait1();
    __syncthreads();

    const int qbase = wq * 32, r = lane >> 2;
    uint32_t qf[2][4][4];
    #pragma unroll
    for (int t = 0; t < 2; t++)
        #pragma unroll
        for (int kc = 0; kc < 4; kc++)
            ldm_x4(qf[t][kc], sb + (uint32_t)((qbase + t * 16 + (lane & 15)) * 144
                                              + (kc * 16 + ((lane >> 4) << 3)) * 2));
    __half2 cq2[4], sq2[4];
    #pragma unroll
    for (int t = 0; t < 2; t++) {
        cq2[2 * t]     = __half2half2(cph[(size_t)bh * Nq + n0 + qbase + t * 16 + r]);
        sq2[2 * t]     = __half2half2(sph[(size_t)bh * Nq + n0 + qbase + t * 16 + r]);
        cq2[2 * t + 1] = __half2half2(cph[(size_t)bh * Nq + n0 + qbase + t * 16 + r + 8]);
        sq2[2 * t + 1] = __half2half2(sph[(size_t)bh * Nq + n0 + qbase + t * 16 + r + 8]);
    }

    uint32_t O[2][8][2];
    #pragma unroll
    for (int t = 0; t < 2; t++)
        #pragma unroll
        for (int i = 0; i < 8; i++) { O[t][i][0] = 0u; O[t][i][1] = 0u; }
    float l[4] = {0.f, 0.f, 0.f, 0.f};

    const int NSTEP = Nq / 128;
    for (int c = 0; c < NSTEP; c++) {
        if (c > 0) { cp_wait1(); __syncthreads(); }
        const uint32_t ku = sb + FLASH_Q + (c & 1) * FLASH_STAGE;
        const uint32_t vu = ku + 18432;
        const __half* ckh = (const __half*)(fsm + FLASH_Q + (c & 1) * FLASH_STAGE + 36864);
        const __half* skh = ckh + 128;
        const __half* mkh = skh + 128;

        uint32_t c0[8][2], c1[8][2];
        #pragma unroll
        for (int g = 0; g < 8; g++) {
            c0[g][0] = 0u; c0[g][1] = 0u; c1[g][0] = 0u; c1[g][1] = 0u;
        }

        // QK^T (fp16 acc, K frags shared by both q-tiles)
        #pragma unroll
        for (int kc = 0; kc < 4; kc++) {
            #pragma unroll
            for (int gp = 0; gp < 4; gp++) {
                uint32_t bb[4];
                const int krow = wn * 64 + gp * 16 + ((lane >> 4) << 3) + (lane & 7);
                ldm_x4(bb, ku + (uint32_t)(krow * 144 + (kc * 16 + (((lane >> 3) & 1) << 3)) * 2));
                mma16816hh(c0[2 * gp],     qf[0][kc], bb);
                mma16816hh(c0[2 * gp + 1], qf[0][kc], bb + 2);
                mma16816hh(c1[2 * gp],     qf[1][kc], bb);
                mma16816hh(c1[2 * gp + 1], qf[1][kc], bb + 2);
            }
        }

        // harmonic + mask + exp2, fully packed half2
        __half2 L[4];
        L[0] = __floats2half2_rn(0.f, 0.f); L[1] = L[0]; L[2] = L[0]; L[3] = L[0];
        #pragma unroll
        for (int g = 0; g < 8; g++) {
            const int kg = wn * 64 + g * 8 + ((lane & 3) << 1);
            const __half2 ck2 = *(const __half2*)(ckh + kg);
            const __half2 sk2 = *(const __half2*)(skh + kg);
            const __half2 mk2 = *(const __half2*)(mkh + kg);
            #pragma unroll
            for (int j = 0; j < 4; j++) {
                uint32_t* cp = (j < 2) ? &c0[g][j] : &c1[g][j - 2];
                const __half2 cv = *(__half2*)cp;
                const __half2 hx = __hfma2(sq2[j], sk2, __hmul2(cq2[j], ck2));
                const __half2 s = __hadd2(__hfma2(cv, hx, cv), mk2);
                const uint32_t p = ex2h2(s);
                *cp = p;
                L[j] = __hadd2(L[j], *(__half2*)&p);
            }
        }
        #pragma unroll
        for (int j = 0; j < 4; j++)
            l[j] += __low2float(L[j]) + __high2float(L[j]);

        // P @ V (fp16 acc, V frags shared)
        #pragma unroll
        for (int kc2 = 0; kc2 < 4; kc2++) {
            uint32_t aA[4], aB[4];
            aA[0] = c0[2 * kc2][0];     aA[1] = c0[2 * kc2][1];
            aA[2] = c0[2 * kc2 + 1][0]; aA[3] = c0[2 * kc2 + 1][1];
            aB[0] = c1[2 * kc2][0];     aB[1] = c1[2 * kc2][1];
            aB[2] = c1[2 * kc2 + 1][0]; aB[3] = c1[2 * kc2 + 1][1];
            const int vrow = wn * 64 + kc2 * 16 + (lane & 15);
            #pragma unroll
            for (int dgp = 0; dgp < 4; dgp++) {
                uint32_t bb[4];
                ldm_x4_t(bb, vu + (uint32_t)(vrow * 144 + (dgp * 16 + ((lane >> 4) << 3)) * 2));
                mma16816hh(O[0][2 * dgp],     aA, bb);
                mma16816hh(O[0][2 * dgp + 1], aA, bb + 2);
                mma16816hh(O[1][2 * dgp],     aB, bb);
                mma16816hh(O[1][2 * dgp + 1], aB, bb + 2);
            }
        }
        __syncthreads();
        if (c + 2 < NSTEP) issueKV(c + 2, c & 1);
    }

    #pragma unroll
    for (int i = 0; i < 4; i++) {
        l[i] += __shfl_xor_sync(~0u, l[i], 1);
        l[i] += __shfl_xor_sync(~0u, l[i], 2);
    }

    // cross-warp (wn) combine via smem
    float* redO = (float*)fsm;                       // [128][66]
    float* redL = (float*)(fsm + 128 * 66 * 4);      // [128]
    if (wn == 1) {
        #pragma unroll
        for (int t = 0; t < 2; t++) {
            const int row0 = qbase + t * 16 + r, row1 = row0 + 8;
            #pragma unroll
            for (int dg = 0; dg < 8; dg++) {
                const int col = dg * 8 + ((lane & 3) << 1);
                const float2 a0 = __half22float2(*(__half2*)&O[t][dg][0]);
                const float2 a1 = __half22float2(*(__half2*)&O[t][dg][1]);
                redO[row0 * 66 + col]     = a0.x;
                redO[row0 * 66 + col + 1] = a0.y;
                redO[row1 * 66 + col]     = a1.x;
                redO[row1 * 66 + col + 1] = a1.y;
            }
            if ((lane & 3) == 0) { redL[row0] = l[2 * t]; redL[row1] = l[2 * t + 1]; }
        }
    }
    __syncthreads();
    if (wn == 0) {
        #pragma unroll
        for (int t = 0; t < 2; t++) {
            const int row0 = qbase + t * 16 + r, row1 = row0 + 8;
            const float i0 = 1.f / (l[2 * t] + redL[row0]);
            const float i1 = 1.f / (l[2 * t + 1] + redL[row1]);
            const size_t gr0 = (size_t)(b * Nq + n0 + row0) * Dq + hh * DHq;
            const size_t gr1 = (size_t)(b * Nq + n0 + row1) * Dq + hh * DHq;
            #pragma unroll
            for (int dg = 0; dg < 8; dg++) {
                const int col = dg * 8 + ((lane & 3) << 1);
                const float2 a0 = __half22float2(*(__half2*)&O[t][dg][0]);
                const float2 a1 = __half22float2(*(__half2*)&O[t][dg][1]);
                *(__half2*)(Mh + gr0 + col) =
                    __floats2half2_rn((a0.x + redO[row0 * 66 + col]) * i0,
                                      (a0.y + redO[row0 * 66 + col + 1]) * i0);
                *(__half2*)(Mh + gr1 + col) =
                    __floats2half2_rn((a1.x + redO[row1 * 66 + col]) * i1,
                                      (a1.y + redO[row1 * 66 + col + 1]) * i1);
            }
        }
    }
}

// ---------------- fused prep: weights transpose + h->fp16 + phases + mask ----
__device__ __forceinline__ void wtile_h(const float* __restrict__ W, __half* __restrict__ T,
                                        int K, int Nc, int k0, int n0, int tx, int ty,
                                        float t[32][33]) {
    #pragma unroll
    for (int i = ty; i < 32; i += 8) t[i][tx] = W[(size_t)(k0 + i) * Nc + n0 + tx];
    __syncthreads();
    #pragma unroll
    for (int i = ty; i < 32; i += 8)
        T[(size_t)(n0 + i) * K + k0 + tx] = __float2half_rn(t[tx][i]);
}

__global__ void prep_kernel(
    const float* Wq, const float* Wk, const float* Wv, const float* Wo,
    const float* W1, const float* W2, const float* h,
    const float* Wp, const float* bp, const unsigned char* mask,
    __half* qkvT, __half* oT, __half* w1T, __half* w2T, __half* h16,
    __half* cph, __half* sph, __half* maskh)
{
    __shared__ float t[32][33];
    __shared__ float w8t[8][516];
    __shared__ float b8s[8];
    const int tx = threadIdx.x, ty = threadIdx.y;
    const int tid = ty * 32 + tx;
    int id = blockIdx.x;
    if (id < 1024) {
        const int w = id >> 8, tl = id & 255;
        const int n0 = (tl & 15) * 32, k0 = (tl >> 4) * 32;
        const float* W = (w == 0) ? Wq : (w == 1) ? Wk : (w == 2) ? Wv : Wo;
        __half* T = (w < 3) ? (qkvT + (size_t)w * Dq * Dq) : oT;
        wtile_h(W, T, Dq, Dq, k0, n0, tx, ty, t);
    } else if (id < 2048) {
        const int tl = id - 1024;
        wtile_h(W1, w1T, Dq, Fq, (tl >> 6) * 32, (tl & 63) * 32, tx, ty, t);
    } else if (id < 3072) {
        const int tl = id - 2048;
        wtile_h(W2, w2T, Fq, Dq, (tl >> 4) * 32, (tl & 15) * 32, tx, ty, t);
    } else if (id < 3584) {
        const size_t base = (size_t)(id - 3072) * 4096 + tid * 16;
        #pragma unroll
        for (int i = 0; i < 4; i++) {
            const float4 v = *(const float4*)(h + base + i * 4);
            *(__half2*)(h16 + base + i * 4)     = __floats2half2_rn(v.x, v.y);
            *(__half2*)(h16 + base + i * 4 + 2) = __floats2half2_rn(v.z, v.w);
        }
    } else if (id == 3584) {
        // mask bytes -> additive fp16 (-100 masked, 0 clear)
        for (int i = tid; i < Bq * Nq; i += 256)
            maskh[i] = __float2half(mask[i] ? -100.f : 0.f);
    } else {
        // phase projection: rows (id-3585)*32 .. +31 ; cos/sin -> fp16
        for (int i = tid; i < Dq * Hq; i += 256) w8t[i & 7][i >> 3] = Wp[i];
        if (tid < 8) b8s[tid] = bp[tid];
        __syncthreads();
        const int warp = tid >> 5, lane = tid & 31;
        #pragma unroll
        for (int rr = 0; rr < 4; rr++) {
            const int row = (id - 3585) * 32 + warp * 4 + rr;
            const float4* X4 = (const float4*)(h + (size_t)row * Dq);
            float acc[8] = {0.f, 0.f, 0.f, 0.f, 0.f, 0.f, 0.f, 0.f};
            #pragma unroll
            for (int i = 0; i < 4; i++) {
                const int c4 = lane + i * 32;
                const float4 xv = X4[c4];
                #pragma unroll
                for (int w = 0; w < 8; w++) {
                    const float4 wv = ((const float4*)&w8t[w][0])[c4];
                    acc[w] += xv.x * wv.x + xv.y * wv.y + xv.z * wv.z + xv.w * wv.w;
                }
            }
            #pragma unroll
            for (int w = 0; w < 8; w++)
                #pragma unroll
                for (int o = 16; o; o >>= 1) acc[w] += __shfl_xor_sync(~0u, acc[w], o);
            if (lane < 8) {
                float s = b8s[lane];
                #pragma unroll
                for (int w = 0; w < 8; w++) if (lane == w) s += acc[w];
                const int b = row >> 11, n = row & 2047;
                cph[(size_t)(b * Hq + lane) * Nq + n] = __float2half(cosf(s));
                sph[(size_t)(b * Hq + lane) * Nq + n] = __float2half(sinf(s));
            }
        }
    }
}

// ---------------- phase update + delta (one launch) ---------------------------
__global__ __launch_bounds__(256) void phase_kernel(
    const float* __restrict__ h2, const float* __restrict__ Wph,
    const float* __restrict__ bph, const float* __restrict__ phases,
    float* __restrict__ out_phases,
    const float* __restrict__ rn, float* __restrict__ out_delta)
{
    if (blockIdx.x == ROWS / 32) {
        __shared__ float red[256];
        const int tid = threadIdx.x;
        float s = 0.f;
        for (int i = tid; i < ROWS; i += 256) s += rn[i];
        red[tid] = s; __syncthreads();
        #pragma unroll
        for (int o = 128; o; o >>= 1) { if (tid < o) red[tid] += red[tid + o]; __syncthreads(); }
        if (tid == 0) out_delta[0] = red[0] * (1.f / ROWS);
        return;
    }
    __shared__ float w8t[8][516];
    __shared__ float b8s[8];
    const int tid = threadIdx.x;
    for (int i = tid; i < Dq * Hq; i += 256) w8t[i & 7][i >> 3] = Wph[i];
    if (tid < 8) b8s[tid] = bph[tid];
    __syncthreads();
    const int warp = tid >> 5, lane = tid & 31;
    #pragma unroll
    for (int rr = 0; rr < 4; rr++) {
        const int row = blockIdx.x * 32 + warp * 4 + rr;
        const float4* X4 = (const float4*)(h2 + (size_t)row * Dq);
        float acc[8] = {0.f, 0.f, 0.f, 0.f, 0.f, 0.f, 0.f, 0.f};
        #pragma unroll
        for (int i = 0; i < 4; i++) {
            const int c4 = lane + i * 32;
            const float4 xv = X4[c4];
            #pragma unroll
            for (int w = 0; w < 8; w++) {
                const float4 wv = ((const float4*)&w8t[w][0])[c4];
                acc[w] += xv.x * wv.x + xv.y * wv.y + xv.z * wv.z + xv.w * wv.w;
            }
        }
        #pragma unroll
        for (int w = 0; w < 8; w++)
            #pragma unroll
            for (int o = 16; o; o >>= 1) acc[w] += __shfl_xor_sync(~0u, acc[w], o);
        if (lane < 8) {
            float s = b8s[lane];
            #pragma unroll
            for (int w = 0; w < 8; w++) if (lane == w) s += acc[w];
            out_phases[(size_t)row * Hq + lane] = phases[(size_t)row * Hq + lane]
                                                  + 0.31415926535897932f * tanhf(s);
        }
    }
}

// ---------------- residual add + LayerNorm (warp per row) --------------------
__global__ __launch_bounds__(256) void addln_kernel(
    const float* __restrict__ X, const float* __restrict__ Y,
    const float* __restrict__ g, const float* __restrict__ be,
    float* __restrict__ out, __half* __restrict__ oh16,
    const float* __restrict__ href, float* __restrict__ rn)
{
    const int warp = threadIdx.x >> 5, lane = threadIdx.x & 31;
    const size_t row = blockIdx.x * 8 + warp;
    const float4* X4 = (const float4*)(X + row * Dq);
    const float4* Y4 = (const float4*)(Y + row * Dq);
    float a[16];
    float s = 0.f;
    #pragma unroll
    for (int i = 0; i < 4; i++) {
        const float4 xv = X4[lane + i * 32];
        const float4 yv = Y4[lane + i * 32];
        a[4 * i + 0] = xv.x + yv.x; a[4 * i + 1] = xv.y + yv.y;
        a[4 * i + 2] = xv.z + yv.z; a[4 * i + 3] = xv.w + yv.w;
        s += a[4 * i] + a[4 * i + 1] + a[4 * i + 2] + a[4 * i + 3];
    }
    #pragma unroll
    for (int o = 16; o; o >>= 1) s += __shfl_xor_sync(~0u, s, o);
    const float mu = s * (1.f / Dq);
    float vs = 0.f;
    #pragma unroll
    for (int i = 0; i < 16; i++) { const float d = a[i] - mu; vs += d * d; }
    #pragma unroll
    for (int o = 16; o; o >>= 1) vs += __shfl_xor_sync(~0u, vs, o);
    const float rstd = rsqrtf(vs * (1.f / Dq) + 1e-5f);
    float ss = 0.f;
    #pragma unroll
    for (int i = 0; i < 4; i++) {
        const int c4 = lane + i * 32;
        const float4 gv = ((const float4*)g)[c4];
        const float4 bv = ((const float4*)be)[c4];
        float4 r;
        r.x = (a[4 * i + 0] - mu) * rstd * gv.x + bv.x;
        r.y = (a[4 * i + 1] - mu) * rstd * gv.y + bv.y;
        r.z = (a[4 * i + 2] - mu) * rstd * gv.z + bv.z;
        r.w = (a[4 * i + 3] - mu) * rstd * gv.w + bv.w;
        ((float4*)(out + row * Dq))[c4] = r;
        if (oh16) {
            *(__half2*)(oh16 + row * Dq + c4 * 4)     = __floats2half2_rn(r.x, r.y);
            *(__half2*)(oh16 + row * Dq + c4 * 4 + 2) = __floats2half2_rn(r.z, r.w);
        }
        if (href) {
            const float4 hv = ((const float4*)(href + row * Dq))[c4];
            const float d0 = r.x - hv.x, d1 = r.y - hv.y, d2 = r.z - hv.z, d3 = r.w - hv.w;
            ss += d0 * d0 + d1 * d1 + d2 * d2 + d3 * d3;
        }
    }
    if (href) {
        #pragma unroll
        for (int o = 16; o; o >>= 1) ss += __shfl_xor_sync(~0u, ss, o);
        if (lane == 0) rn[row] = sqrtf(ss);
    }
}

// ---------------- launch ------------------------------------------------------
extern "C" void kernel_launch(void* const* d_in, const int* in_sizes, int n_in,
                              void* d_out, int out_size) {
    const float* h      = (const float*)d_in[0];
    const float* phases = (const float*)d_in[1];
    const unsigned char* mask = (const unsigned char*)d_in[2];
    const float* Wq  = (const float*)d_in[3];
    const float* Wk  = (const float*)d_in[4];
    const float* Wp  = (const float*)d_in[5];
    const float* bp  = (const float*)d_in[6];
    const float* Wv  = (const float*)d_in[7];
    const float* Wo  = (const float*)d_in[8];
    const float* W1  = (const float*)d_in[9];
    const float* b1  = (const float*)d_in[10];
    const float* W2  = (const float*)d_in[11];
    const float* b2  = (const float*)d_in[12];
    const float* g1  = (const float*)d_in[13];
    const float* be1 = (const float*)d_in[14];
    const float* g2  = (const float*)d_in[15];
    const float* be2 = (const float*)d_in[16];
    const float* Wph = (const float*)d_in[17];
    const float* bph = (const float*)d_in[18];

    float* out_h2     = (float*)d_out;
    float* out_phases = out_h2 + (size_t)ROWS * Dq;
    float* out_delta  = out_phases + (size_t)ROWS * Hq;

    float *msgO, *h1, *ffn2, *rn;
    __half *QKVh, *h16, *mh, *h1h, *f1h, *WqkvT, *WoT, *W1T, *W2T, *cphh, *sphh, *maskhp;
    cudaGetSymbolAddress((void**)&msgO, g_msgO);
    cudaGetSymbolAddress((void**)&h1, g_h1);    cudaGetSymbolAddress((void**)&ffn2, g_ffn2);
    cudaGetSymbolAddress((void**)&rn, g_rn);
    cudaGetSymbolAddress((void**)&QKVh, g_QKVh);
    cudaGetSymbolAddress((void**)&h16, g_h16);
    cudaGetSymbolAddress((void**)&mh, g_mh);
    cudaGetSymbolAddress((void**)&h1h, g_h1h);
    cudaGetSymbolAddress((void**)&f1h, g_ffn1h);
    cudaGetSymbolAddress((void**)&WqkvT, g_WqkvT);
    cudaGetSymbolAddress((void**)&WoT, g_WoT);
    cudaGetSymbolAddress((void**)&W1T, g_W1T);
    cudaGetSymbolAddress((void**)&W2T, g_W2T);
    cudaGetSymbolAddress((void**)&cphh, g_cph16);
    cudaGetSymbolAddress((void**)&sphh, g_sph16);
    cudaGetSymbolAddress((void**)&maskhp, g_mask16);

    const int smG = 4 * 2 * TILE_B;           // 81920
    cudaFuncSetAttribute(flash_kernel, cudaFuncAttributeMaxDynamicSharedMemorySize, FLASH_SMEM);
    cudaFuncSetAttribute((const void*)tgemm_kernel<4>, cudaFuncAttributeMaxDynamicSharedMemorySize, smG);

    // prep: weight transpose + h->fp16 + phase cos/sin + mask convert
    prep_kernel<<<3713, dim3(32, 8)>>>(Wq, Wk, Wv, Wo, W1, W2, h, Wp, bp, mask,
                                       WqkvT, WoT, W1T, W2T, h16, cphh, sphh, maskhp);

    // fused QKV projection -> fp16 (Q cols scaled by log2e/16)
    tgemm_kernel<4><<<dim3(QKVS / 128, ROWS / 128), 256, smG>>>(
        h16, WqkvT, nullptr, nullptr, QKVh, Dq, QKVS, 8 | 16);

    // fused flash attention
    flash_kernel<<<dim3(Nq / 128, BHq), 256, FLASH_SMEM>>>(QKVh, cphh, sphh, maskhp, mh);

    // Wo projection (fp16 -> fp32)
    tgemm_kernel<4><<<dim3(Dq / 128, ROWS / 128), 256, smG>>>(
        mh, WoT, nullptr, msgO, nullptr, Dq, Dq, 0);
    addln_kernel<<<ROWS / 8, 256>>>(h, msgO, g1, be1, h1, h1h, nullptr, nullptr);

    // FFN (fp16)
    tgemm_kernel<4><<<dim3(Fq / 128, ROWS / 128), 256, smG>>>(
        h1h, W1T, b1, nullptr, f1h, Dq, Fq, 11);
    tgemm_kernel<4><<<dim3(Dq / 128, ROWS / 128), 256, smG>>>(
        f1h, W2T, b2, ffn2, nullptr, Fq, Dq, 1);
    addln_kernel<<<ROWS / 8, 256>>>(h1, ffn2, g2, be2, out_h2, nullptr, h, rn);

    // phase update + delta (one launch)
    phase_kernel<<<ROWS / 32 + 1, 256>>>(out_h2, Wph, bph, phases, out_phases, rn, out_delta);
}

// round 13
// speedup vs baseline: 1.0837x; 1.0837x over previous
#include <cuda_runtime.h>
#include <cuda_bf16.h>
#include <cuda_fp16.h>
#include <math.h>
#include <stdint.h>

#define Bq 2
#define Nq 2048
#define Dq 512
#define Hq 8
#define Fq 2048
#define DHq 64
#define ROWS (Bq*Nq)            // 4096
#define BHq (Bq*Hq)             // 16
#define QKVS (3*Dq)             // 1536
#define QSCL 0.0901684403f      // (1/16) * log2(e)

// ---------------- scratch (static device globals) ---------------------------
__device__ float g_msgO[ROWS*Dq];
__device__ float g_h1[ROWS*Dq];
__device__ float g_ffn2[ROWS*Dq];
__device__ float g_rn[ROWS];

__device__ __half g_QKVh[(size_t)ROWS*QKVS];
__device__ __half g_h16[ROWS*Dq];
__device__ __half g_mh[ROWS*Dq];
__device__ __half g_h1h[ROWS*Dq];
__device__ __half g_ffn1h[(size_t)ROWS*Fq];
__device__ __half g_WqkvT[3*Dq*Dq];
__device__ __half g_WoT[Dq*Dq];
__device__ __half g_W1T[(size_t)Fq*Dq];
__device__ __half g_W2T[(size_t)Dq*Fq];
__device__ __half g_cph16[BHq*Nq];
__device__ __half g_sph16[BHq*Nq];
__device__ __half g_mask16[Bq*Nq];

// ---------------- PTX helpers -----------------------------------------------
__device__ __forceinline__ uint32_t smem_u32(const void* p) {
    return (uint32_t)__cvta_generic_to_shared(p);
}
__device__ __forceinline__ void cp16(uint32_t s, const void* g) {
    asm volatile("cp.async.cg.shared.global [%0], [%1], 16;" :: "r"(s), "l"(g));
}
__device__ __forceinline__ void cp_commit() { asm volatile("cp.async.commit_group;" ::: "memory"); }
__device__ __forceinline__ void cp_wait1()  { asm volatile("cp.async.wait_group 1;" ::: "memory"); }

__device__ __forceinline__ void ldm_x4(uint32_t* r, uint32_t addr) {
    asm volatile("ldmatrix.sync.aligned.m8n8.x4.shared.b16 {%0,%1,%2,%3}, [%4];"
                 : "=r"(r[0]), "=r"(r[1]), "=r"(r[2]), "=r"(r[3]) : "r"(addr));
}
__device__ __forceinline__ void ldm_x4_t(uint32_t* r, uint32_t addr) {
    asm volatile("ldmatrix.sync.aligned.m8n8.x4.trans.shared.b16 {%0,%1,%2,%3}, [%4];"
                 : "=r"(r[0]), "=r"(r[1]), "=r"(r[2]), "=r"(r[3]) : "r"(addr));
}
__device__ __forceinline__ void mma16816h(float* c, const uint32_t* a, const uint32_t* b) {
    asm volatile("mma.sync.aligned.m16n8k16.row.col.f32.f16.f16.f32 "
                 "{%0,%1,%2,%3}, {%4,%5,%6,%7}, {%8,%9}, {%0,%1,%2,%3};"
                 : "+f"(c[0]), "+f"(c[1]), "+f"(c[2]), "+f"(c[3])
                 : "r"(a[0]), "r"(a[1]), "r"(a[2]), "r"(a[3]), "r"(b[0]), "r"(b[1]));
}
__device__ __forceinline__ void mma16816hh(uint32_t* c, const uint32_t* a, const uint32_t* b) {
    asm volatile("mma.sync.aligned.m16n8k16.row.col.f16.f16.f16.f16 "
                 "{%0,%1}, {%2,%3,%4,%5}, {%6,%7}, {%0,%1};"
                 : "+r"(c[0]), "+r"(c[1])
                 : "r"(a[0]), "r"(a[1]), "r"(a[2]), "r"(a[3]), "r"(b[0]), "r"(b[1]));
}
__device__ __forceinline__ uint32_t ex2h2(__half2 s) {
    uint32_t r;
    asm("ex2.approx.f16x2 %0, %1;" : "=r"(r) : "r"(*(uint32_t*)&s));
    return r;
}

// ---------------- HMMA fp16 GEMM: C = A(MxK) @ BT(NxK)^T ---------------------
// epi bit0: +bias ; bit1: GELU ; bit3: fp16 out ; bit4: scale cols<Dq by QSCL
#define TSTR 40
#define TILE_B (128 * TSTR * 2)         // 10240 bytes per tile
template<int STAGES>
__global__ __launch_bounds__(256) void tgemm_kernel(
    const __half* __restrict__ A, const __half* __restrict__ B,
    const float* __restrict__ bias,
    float* __restrict__ Cf, __half* __restrict__ C16,
    int K, int Nc, int epi)
{
    extern __shared__ __align__(128) unsigned char dsm[];
    const uint32_t stg = 2 * TILE_B;
    const uint32_t sb = smem_u32(dsm);
    const int tid = threadIdx.x;
    const int warp = tid >> 5, lane = tid & 31;
    const int wm = warp >> 1, wn = warp & 1;
    const int bm = blockIdx.y * 128, bn = blockIdx.x * 128;

    const int NCH = K >> 5;
    const int lrow = tid >> 2, lch = (tid & 3) << 3;

    float acc[2][8][4];
    #pragma unroll
    for (int i = 0; i < 2; i++)
        #pragma unroll
        for (int j = 0; j < 8; j++)
            #pragma unroll
            for (int q = 0; q < 4; q++) acc[i][j][q] = 0.f;

    auto issue = [&](int c) {
        if (c < NCH) {
            const int kc = c << 5;
            const uint32_t base = sb + (uint32_t)(c % STAGES) * stg;
            #pragma unroll
            for (int i = 0; i < 2; i++) {
                const int row = lrow + i * 64;
                const uint32_t so = (uint32_t)(row * TSTR + lch) * 2;
                cp16(base + so,          A + (size_t)(bm + row) * K + kc + lch);
                cp16(base + TILE_B + so, B + (size_t)(bn + row) * K + kc + lch);
            }
        }
        cp_commit();
    };

    #pragma unroll
    for (int p = 0; p < STAGES - 1; p++) issue(p);

    for (int c = 0; c < NCH; c++) {
        asm volatile("cp.async.wait_group %0;" :: "n"(STAGES - 2));
        __syncthreads();
        issue(c + STAGES - 1);
        const uint32_t base = sb + (uint32_t)(c % STAGES) * stg;
        #pragma unroll
        for (int ks = 0; ks < 2; ks++) {
            const uint32_t arow = (uint32_t)((wm * 32 + (lane & 15)) * TSTR
                                             + ks * 16 + ((lane >> 4) << 3)) * 2;
            const uint32_t brow = (uint32_t)((wn * 64 + ((lane >> 4) << 3) + (lane & 7)) * TSTR
                                             + ks * 16 + (((lane >> 3) & 1) << 3)) * 2;
            uint32_t aH[2][4], bH[4][4];
            #pragma unroll
            for (int mt = 0; mt < 2; mt++)
                ldm_x4(aH[mt], base + arow + (uint32_t)(mt * 16 * TSTR) * 2);
            #pragma unroll
            for (int nt4 = 0; nt4 < 4; nt4++)
                ldm_x4(bH[nt4], base + TILE_B + brow + (uint32_t)(nt4 * 16 * TSTR) * 2);
            #pragma unroll
            for (int mt = 0; mt < 2; mt++)
                #pragma unroll
                for (int nt = 0; nt < 8; nt++)
                    mma16816h(acc[mt][nt], aH[mt], &bH[nt >> 1][(nt & 1) * 2]);
        }
        __syncthreads();
    }

    #pragma unroll
    for (int mt = 0; mt < 2; mt++) {
        const int r0 = bm + wm * 32 + mt * 16 + (lane >> 2);
        #pragma unroll
        for (int nt = 0; nt < 8; nt++) {
            const int gn = bn + wn * 64 + nt * 8 + ((lane & 3) << 1);
            #pragma unroll
            for (int half = 0; half < 2; half++) {
                const int row = r0 + half * 8;
                float v0 = acc[mt][nt][half * 2 + 0];
                float v1 = acc[mt][nt][half * 2 + 1];
                if (epi & 1) { v0 += bias[gn]; v1 += bias[gn + 1]; }
                if (epi & 2) {
                    v0 = 0.5f * v0 * (1.f + erff(v0 * 0.7071067811865475f));
                    v1 = 0.5f * v1 * (1.f + erff(v1 * 0.7071067811865475f));
                }
                if ((epi & 16) && gn < Dq) { v0 *= QSCL; v1 *= QSCL; }
                const size_t idx = (size_t)row * Nc + gn;
                if (epi & 8) {
                    *(__half2*)(C16 + idx) = __floats2half2_rn(v0, v1);
                } else {
                    *(float2*)(Cf + idx) = make_float2(v0, v1);
                }
            }
        }
    }
}

// ---------------- fused flash attention (fp16 acc, half2 harmonic) -----------
// Q pre-scaled by log2e/16. grid (Nq/128, BHq), 256 threads (8 warps).
// Warp: wq = warp&3 -> queries wq*32..+31 (2 tiles), wn = warp>>2 -> keys wn*64..+63.
#define FLASH_STAGE 37632
#define FLASH_Q     18432
#define FLASH_SMEM  (FLASH_Q + 2 * FLASH_STAGE)     // 93696
__global__ __launch_bounds__(256, 2) void flash_kernel(
    const __half* __restrict__ QKV,
    const __half* __restrict__ cph, const __half* __restrict__ sph,
    const __half* __restrict__ maskh,
    __half* __restrict__ Mh)
{
    extern __shared__ __align__(128) unsigned char fsm[];
    const int tid = threadIdx.x, warp = tid >> 5, lane = tid & 31;
    const int wq = warp & 3, wn = warp >> 2;
    const int bh = blockIdx.y, b = bh >> 3, hh = bh & 7;
    const int n0 = blockIdx.x * 128;
    const uint32_t sb = smem_u32(fsm);

    const __half* gQ = QKV + ((size_t)b * Nq + n0) * QKVS + hh * DHq;
    #pragma unroll
    for (int i = 0; i < 4; i++) {
        const int id = tid + i * 256, row = id >> 3, ch = id & 7;
        cp16(sb + row * 144 + ch * 16, gQ + (size_t)row * QKVS + ch * 8);
    }
    cp_commit();

    auto issueKV = [&](int step, int s) {
        const uint32_t ku = sb + FLASH_Q + s * FLASH_STAGE;
        const uint32_t vu = ku + 18432, cku = ku + 36864, sku = ku + 37120, mku = ku + 37376;
        const __half* gK = QKV + ((size_t)b * Nq + step * 128) * QKVS + Dq + hh * DHq;
        const __half* gV = gK + Dq;
        #pragma unroll
        for (int i = 0; i < 4; i++) {
            const int id = tid + i * 256, row = id >> 3, ch = id & 7;
            cp16(ku + row * 144 + ch * 16, gK + (size_t)row * QKVS + ch * 8);
            cp16(vu + row * 144 + ch * 16, gV + (size_t)row * QKVS + ch * 8);
        }
        if (tid < 16)      cp16(cku + tid * 16, cph + (size_t)bh * Nq + step * 128 + tid * 8);
        else if (tid < 32) cp16(sku + (tid - 16) * 16, sph + (size_t)bh * Nq + step * 128 + (tid - 16) * 8);
        else if (tid < 48) cp16(mku + (tid - 32) * 16, maskh + (size_t)b * Nq + step * 128 + (tid - 32) * 8);
        cp_commit();
    };
    issueKV(0, 0);
    issueKV(1, 1);
    cp_wait1();
    __syncthreads();

    const int qbase = wq * 32, r = lane >> 2;
    uint32_t qf[2][4][4];
    #pragma unroll
    for (int t = 0; t < 2; t++)
        #pragma unroll
        for (int kc = 0; kc < 4; kc++)
            ldm_x4(qf[t][kc], sb + (uint32_t)((qbase + t * 16 + (lane & 15)) * 144
                                              + (kc * 16 + ((lane >> 4) << 3)) * 2));
    const __half2 cqA = __half2half2(cph[(size_t)bh * Nq + n0 + qbase + r]);
    const __half2 sqA = __half2half2(sph[(size_t)bh * Nq + n0 + qbase + r]);
    const __half2 cqB = __half2half2(cph[(size_t)bh * Nq + n0 + qbase + r + 8]);
    const __half2 sqB = __half2half2(sph[(size_t)bh * Nq + n0 + qbase + r + 8]);
    const __half2 cqC = __half2half2(cph[(size_t)bh * Nq + n0 + qbase + 16 + r]);
    const __half2 sqC = __half2half2(sph[(size_t)bh * Nq + n0 + qbase + 16 + r]);
    const __half2 cqD = __half2half2(cph[(size_t)bh * Nq + n0 + qbase + 16 + r + 8]);
    const __half2 sqD = __half2half2(sph[(size_t)bh * Nq + n0 + qbase + 16 + r + 8]);

    uint32_t O[2][8][2];
    #pragma unroll
    for (int t = 0; t < 2; t++)
        #pragma unroll
        for (int i = 0; i < 8; i++) { O[t][i][0] = 0u; O[t][i][1] = 0u; }
    float l[4] = {0.f, 0.f, 0.f, 0.f};

    const int NSTEP = Nq / 128;
    for (int c = 0; c < NSTEP; c++) {
        if (c > 0) { cp_wait1(); __syncthreads(); }
        const uint32_t ku = sb + FLASH_Q + (c & 1) * FLASH_STAGE;
        const uint32_t vu = ku + 18432;
        const __half* ckh = (const __half*)(fsm + FLASH_Q + (c & 1) * FLASH_STAGE + 36864);
        const __half* skh = ckh + 128;
        const __half* mkh = skh + 128;

        uint32_t c0[8][2], c1[8][2];
        #pragma unroll
        for (int g = 0; g < 8; g++) {
            c0[g][0] = 0u; c0[g][1] = 0u; c1[g][0] = 0u; c1[g][1] = 0u;
        }

        // QK^T (fp16 acc, K frags shared by both q-tiles)
        #pragma unroll
        for (int kc = 0; kc < 4; kc++) {
            #pragma unroll
            for (int gp = 0; gp < 4; gp++) {
                uint32_t bb[4];
                const int krow = wn * 64 + gp * 16 + ((lane >> 4) << 3) + (lane & 7);
                ldm_x4(bb, ku + (uint32_t)(krow * 144 + (kc * 16 + (((lane >> 3) & 1) << 3)) * 2));
                mma16816hh(c0[2 * gp],     qf[0][kc], bb);
                mma16816hh(c0[2 * gp + 1], qf[0][kc], bb + 2);
                mma16816hh(c1[2 * gp],     qf[1][kc], bb);
                mma16816hh(c1[2 * gp + 1], qf[1][kc], bb + 2);
            }
        }

        // harmonic + mask + exp2, fully packed half2, explicit (no reg-array ptrs)
        __half2 L0 = __floats2half2_rn(0.f, 0.f), L1 = L0, L2 = L0, L3 = L0;
        #pragma unroll
        for (int g = 0; g < 8; g++) {
            const int kg = wn * 64 + g * 8 + ((lane & 3) << 1);
            const __half2 ck2 = *(const __half2*)(ckh + kg);
            const __half2 sk2 = *(const __half2*)(skh + kg);
            const __half2 mk2 = *(const __half2*)(mkh + kg);
            {   // q-rows r (tile 0)
                const __half2 cv = *(__half2*)&c0[g][0];
                const __half2 hx = __hfma2(sqA, sk2, __hmul2(cqA, ck2));
                const uint32_t p = ex2h2(__hadd2(__hfma2(cv, hx, cv), mk2));
                c0[g][0] = p;
                L0 = __hadd2(L0, *(__half2*)&p);
            }
            {   // q-rows r+8 (tile 0)
                const __half2 cv = *(__half2*)&c0[g][1];
                const __half2 hx = __hfma2(sqB, sk2, __hmul2(cqB, ck2));
                const uint32_t p = ex2h2(__hadd2(__hfma2(cv, hx, cv), mk2));
                c0[g][1] = p;
                L1 = __hadd2(L1, *(__half2*)&p);
            }
            {   // q-rows r (tile 1)
                const __half2 cv = *(__half2*)&c1[g][0];
                const __half2 hx = __hfma2(sqC, sk2, __hmul2(cqC, ck2));
                const uint32_t p = ex2h2(__hadd2(__hfma2(cv, hx, cv), mk2));
                c1[g][0] = p;
                L2 = __hadd2(L2, *(__half2*)&p);
            }
            {   // q-rows r+8 (tile 1)
                const __half2 cv = *(__half2*)&c1[g][1];
                const __half2 hx = __hfma2(sqD, sk2, __hmul2(cqD, ck2));
                const uint32_t p = ex2h2(__hadd2(__hfma2(cv, hx, cv), mk2));
                c1[g][1] = p;
                L3 = __hadd2(L3, *(__half2*)&p);
            }
        }
        l[0] += __low2float(L0) + __high2float(L0);
        l[1] += __low2float(L1) + __high2float(L1);
        l[2] += __low2float(L2) + __high2float(L2);
        l[3] += __low2float(L3) + __high2float(L3);

        // P @ V (fp16 acc, V frags shared)
        #pragma unroll
        for (int kc2 = 0; kc2 < 4; kc2++) {
            uint32_t aA[4], aB[4];
            aA[0] = c0[2 * kc2][0];     aA[1] = c0[2 * kc2][1];
            aA[2] = c0[2 * kc2 + 1][0]; aA[3] = c0[2 * kc2 + 1][1];
            aB[0] = c1[2 * kc2][0];     aB[1] = c1[2 * kc2][1];
            aB[2] = c1[2 * kc2 + 1][0]; aB[3] = c1[2 * kc2 + 1][1];
            const int vrow = wn * 64 + kc2 * 16 + (lane & 15);
            #pragma unroll
            for (int dgp = 0; dgp < 4; dgp++) {
                uint32_t bb[4];
                ldm_x4_t(bb, vu + (uint32_t)(vrow * 144 + (dgp * 16 + ((lane >> 4) << 3)) * 2));
                mma16816hh(O[0][2 * dgp],     aA, bb);
                mma16816hh(O[0][2 * dgp + 1], aA, bb + 2);
                mma16816hh(O[1][2 * dgp],     aB, bb);
                mma16816hh(O[1][2 * dgp + 1], aB, bb + 2);
            }
        }
        __syncthreads();
        if (c + 2 < NSTEP) issueKV(c + 2, c & 1);
    }

    #pragma unroll
    for (int i = 0; i < 4; i++) {
        l[i] += __shfl_xor_sync(~0u, l[i], 1);
        l[i] += __shfl_xor_sync(~0u, l[i], 2);
    }

    // cross-warp (wn) combine via smem
    float* redO = (float*)fsm;                       // [128][66]
    float* redL = (float*)(fsm + 128 * 66 * 4);      // [128]
    if (wn == 1) {
        #pragma unroll
        for (int t = 0; t < 2; t++) {
            const int row0 = qbase + t * 16 + r, row1 = row0 + 8;
            #pragma unroll
            for (int dg = 0; dg < 8; dg++) {
                const int col = dg * 8 + ((lane & 3) << 1);
                const float2 a0 = __half22float2(*(__half2*)&O[t][dg][0]);
                const float2 a1 = __half22float2(*(__half2*)&O[t][dg][1]);
                redO[row0 * 66 + col]     = a0.x;
                redO[row0 * 66 + col + 1] = a0.y;
                redO[row1 * 66 + col]     = a1.x;
                redO[row1 * 66 + col + 1] = a1.y;
            }
            if ((lane & 3) == 0) { redL[row0] = l[2 * t]; redL[row1] = l[2 * t + 1]; }
        }
    }
    __syncthreads();
    if (wn == 0) {
        #pragma unroll
        for (int t = 0; t < 2; t++) {
            const int row0 = qbase + t * 16 + r, row1 = row0 + 8;
            const float i0 = 1.f / (l[2 * t] + redL[row0]);
            const float i1 = 1.f / (l[2 * t + 1] + redL[row1]);
            const size_t gr0 = (size_t)(b * Nq + n0 + row0) * Dq + hh * DHq;
            const size_t gr1 = (size_t)(b * Nq + n0 + row1) * Dq + hh * DHq;
            #pragma unroll
            for (int dg = 0; dg < 8; dg++) {
                const int col = dg * 8 + ((lane & 3) << 1);
                const float2 a0 = __half22float2(*(__half2*)&O[t][dg][0]);
                const float2 a1 = __half22float2(*(__half2*)&O[t][dg][1]);
                *(__half2*)(Mh + gr0 + col) =
                    __floats2half2_rn((a0.x + redO[row0 * 66 + col]) * i0,
                                      (a0.y + redO[row0 * 66 + col + 1]) * i0);
                *(__half2*)(Mh + gr1 + col) =
                    __floats2half2_rn((a1.x + redO[row1 * 66 + col]) * i1,
                                      (a1.y + redO[row1 * 66 + col + 1]) * i1);
            }
        }
    }
}

// ---------------- fused weight transpose + h convert + mask (one launch) -----
__device__ __forceinline__ void wtile_h(const float* __restrict__ W, __half* __restrict__ T,
                                        int K, int Nc, int k0, int n0, int tx, int ty,
                                        float t[32][33]) {
    #pragma unroll
    for (int i = ty; i < 32; i += 8) t[i][tx] = W[(size_t)(k0 + i) * Nc + n0 + tx];
    __syncthreads();
    #pragma unroll
    for (int i = ty; i < 32; i += 8)
        T[(size_t)(n0 + i) * K + k0 + tx] = __float2half_rn(t[tx][i]);
}

__global__ void wtrans_all_kernel(
    const float* Wq, const float* Wk, const float* Wv, const float* Wo,
    const float* W1, const float* W2, const float* h, const unsigned char* mask,
    __half* qkvT, __half* oT, __half* w1T, __half* w2T, __half* h16, __half* maskh)
{
    __shared__ float t[32][33];
    const int tx = threadIdx.x, ty = threadIdx.y;
    const int tid = ty * 32 + tx;
    int id = blockIdx.x;
    if (id < 1024) {
        const int w = id >> 8, tl = id & 255;
        const int n0 = (tl & 15) * 32, k0 = (tl >> 4) * 32;
        const float* W = (w == 0) ? Wq : (w == 1) ? Wk : (w == 2) ? Wv : Wo;
        __half* T = (w < 3) ? (qkvT + (size_t)w * Dq * Dq) : oT;
        wtile_h(W, T, Dq, Dq, k0, n0, tx, ty, t);
    } else if (id < 2048) {
        const int tl = id - 1024;
        wtile_h(W1, w1T, Dq, Fq, (tl >> 6) * 32, (tl & 63) * 32, tx, ty, t);
    } else if (id < 3072) {
        const int tl = id - 2048;
        wtile_h(W2, w2T, Fq, Dq, (tl >> 4) * 32, (tl & 15) * 32, tx, ty, t);
    } else if (id < 3584) {
        const size_t base = (size_t)(id - 3072) * 4096 + tid * 16;
        #pragma unroll
        for (int i = 0; i < 4; i++) {
            const float4 v = *(const float4*)(h + base + i * 4);
            *(__half2*)(h16 + base + i * 4)     = __floats2half2_rn(v.x, v.y);
            *(__half2*)(h16 + base + i * 4 + 2) = __floats2half2_rn(v.z, v.w);
        }
    } else {
        for (int i = tid; i < Bq * Nq; i += 256)
            maskh[i] = __float2half(mask[i] ? -100.f : 0.f);
    }
}

// ---------------- 8-wide projection: cos/sin->fp16 (mode0) / phases (mode1) --
__global__ __launch_bounds__(256) void proj8_kernel(
    const float* __restrict__ X, const float* __restrict__ W8,
    const float* __restrict__ b8, const float* __restrict__ phases,
    float* __restrict__ out, __half* __restrict__ cph, __half* __restrict__ sph, int mode)
{
    __shared__ float w8t[8][516];
    __shared__ float b8s[8];
    const int tid = threadIdx.x;
    for (int i = tid; i < Dq * Hq; i += 256) w8t[i & 7][i >> 3] = W8[i];
    if (tid < 8) b8s[tid] = b8[tid];
    __syncthreads();
    const int warp = tid >> 5, lane = tid & 31;
    #pragma unroll
    for (int rr = 0; rr < 4; rr++) {
        const int row = blockIdx.x * 32 + warp * 4 + rr;
        const float4* X4 = (const float4*)(X + (size_t)row * Dq);
        float acc[8] = {0.f, 0.f, 0.f, 0.f, 0.f, 0.f, 0.f, 0.f};
        #pragma unroll
        for (int i = 0; i < 4; i++) {
            const int c4 = lane + i * 32;
            const float4 xv = X4[c4];
            #pragma unroll
            for (int w = 0; w < 8; w++) {
                const float4 wv = ((const float4*)&w8t[w][0])[c4];
                acc[w] += xv.x * wv.x + xv.y * wv.y + xv.z * wv.z + xv.w * wv.w;
            }
        }
        #pragma unroll
        for (int w = 0; w < 8; w++)
            #pragma unroll
            for (int o = 16; o; o >>= 1) acc[w] += __shfl_xor_sync(~0u, acc[w], o);
        if (lane < 8) {
            float s = b8s[lane];
            #pragma unroll
            for (int w = 0; w < 8; w++) if (lane == w) s += acc[w];
            if (mode) {
                out[(size_t)row * Hq + lane] = phases[(size_t)row * Hq + lane]
                                               + 0.31415926535897932f * tanhf(s);
            } else {
                const int b = row >> 11, n = row & 2047;
                cph[(size_t)(b * Hq + lane) * Nq + n] = __float2half(cosf(s));
                sph[(size_t)(b * Hq + lane) * Nq + n] = __float2half(sinf(s));
            }
        }
    }
}

// ---------------- residual add + LayerNorm (warp per row) --------------------
__global__ __launch_bounds__(256) void addln_kernel(
    const float* __restrict__ X, const float* __restrict__ Y,
    const float* __restrict__ g, const float* __restrict__ be,
    float* __restrict__ out, __half* __restrict__ oh16,
    const float* __restrict__ href, float* __restrict__ rn)
{
    const int warp = threadIdx.x >> 5, lane = threadIdx.x & 31;
    const size_t row = blockIdx.x * 8 + warp;
    const float4* X4 = (const float4*)(X + row * Dq);
    const float4* Y4 = (const float4*)(Y + row * Dq);
    float a[16];
    float s = 0.f;
    #pragma unroll
    for (int i = 0; i < 4; i++) {
        const float4 xv = X4[lane + i * 32];
        const float4 yv = Y4[lane + i * 32];
        a[4 * i + 0] = xv.x + yv.x; a[4 * i + 1] = xv.y + yv.y;
        a[4 * i + 2] = xv.z + yv.z; a[4 * i + 3] = xv.w + yv.w;
        s += a[4 * i] + a[4 * i + 1] + a[4 * i + 2] + a[4 * i + 3];
    }
    #pragma unroll
    for (int o = 16; o; o >>= 1) s += __shfl_xor_sync(~0u, s, o);
    const float mu = s * (1.f / Dq);
    float vs = 0.f;
    #pragma unroll
    for (int i = 0; i < 16; i++) { const float d = a[i] - mu; vs += d * d; }
    #pragma unroll
    for (int o = 16; o; o >>= 1) vs += __shfl_xor_sync(~0u, vs, o);
    const float rstd = rsqrtf(vs * (1.f / Dq) + 1e-5f);
    float ss = 0.f;
    #pragma unroll
    for (int i = 0; i < 4; i++) {
        const int c4 = lane + i * 32;
        const float4 gv = ((const float4*)g)[c4];
        const float4 bv = ((const float4*)be)[c4];
        float4 r;
        r.x = (a[4 * i + 0] - mu) * rstd * gv.x + bv.x;
        r.y = (a[4 * i + 1] - mu) * rstd * gv.y + bv.y;
        r.z = (a[4 * i + 2] - mu) * rstd * gv.z + bv.z;
        r.w = (a[4 * i + 3] - mu) * rstd * gv.w + bv.w;
        ((float4*)(out + row * Dq))[c4] = r;
        if (oh16) {
            *(__half2*)(oh16 + row * Dq + c4 * 4)     = __floats2half2_rn(r.x, r.y);
            *(__half2*)(oh16 + row * Dq + c4 * 4 + 2) = __floats2half2_rn(r.z, r.w);
        }
        if (href) {
            const float4 hv = ((const float4*)(href + row * Dq))[c4];
            const float d0 = r.x - hv.x, d1 = r.y - hv.y, d2 = r.z - hv.z, d3 = r.w - hv.w;
            ss += d0 * d0 + d1 * d1 + d2 * d2 + d3 * d3;
        }
    }
    if (href) {
        #pragma unroll
        for (int o = 16; o; o >>= 1) ss += __shfl_xor_sync(~0u, ss, o);
        if (lane == 0) rn[row] = sqrtf(ss);
    }
}

__global__ void delta_kernel(const float* __restrict__ rn, float* __restrict__ out) {
    __shared__ float red[256];
    const int tid = threadIdx.x;
    float s = 0.f;
    for (int i = tid; i < ROWS; i += 256) s += rn[i];
    red[tid] = s; __syncthreads();
    #pragma unroll
    for (int o = 128; o; o >>= 1) { if (tid < o) red[tid] += red[tid + o]; __syncthreads(); }
    if (tid == 0) out[0] = red[0] * (1.f / ROWS);
}

// ---------------- launch ------------------------------------------------------
extern "C" void kernel_launch(void* const* d_in, const int* in_sizes, int n_in,
                              void* d_out, int out_size) {
    const float* h      = (const float*)d_in[0];
    const float* phases = (const float*)d_in[1];
    const unsigned char* mask = (const unsigned char*)d_in[2];
    const float* Wq  = (const float*)d_in[3];
    const float* Wk  = (const float*)d_in[4];
    const float* Wp  = (const float*)d_in[5];
    const float* bp  = (const float*)d_in[6];
    const float* Wv  = (const float*)d_in[7];
    const float* Wo  = (const float*)d_in[8];
    const float* W1  = (const float*)d_in[9];
    const float* b1  = (const float*)d_in[10];
    const float* W2  = (const float*)d_in[11];
    const float* b2  = (const float*)d_in[12];
    const float* g1  = (const float*)d_in[13];
    const float* be1 = (const float*)d_in[14];
    const float* g2  = (const float*)d_in[15];
    const float* be2 = (const float*)d_in[16];
    const float* Wph = (const float*)d_in[17];
    const float* bph = (const float*)d_in[18];

    float* out_h2     = (float*)d_out;
    float* out_phases = out_h2 + (size_t)ROWS * Dq;
    float* out_delta  = out_phases + (size_t)ROWS * Hq;

    float *msgO, *h1, *ffn2, *rn;
    __half *QKVh, *h16, *mh, *h1h, *f1h, *WqkvT, *WoT, *W1T, *W2T, *cphh, *sphh, *maskhp;
    cudaGetSymbolAddress((void**)&msgO, g_msgO);
    cudaGetSymbolAddress((void**)&h1, g_h1);    cudaGetSymbolAddress((void**)&ffn2, g_ffn2);
    cudaGetSymbolAddress((void**)&rn, g_rn);
    cudaGetSymbolAddress((void**)&QKVh, g_QKVh);
    cudaGetSymbolAddress((void**)&h16, g_h16);
    cudaGetSymbolAddress((void**)&mh, g_mh);
    cudaGetSymbolAddress((void**)&h1h, g_h1h);
    cudaGetSymbolAddress((void**)&f1h, g_ffn1h);
    cudaGetSymbolAddress((void**)&WqkvT, g_WqkvT);
    cudaGetSymbolAddress((void**)&WoT, g_WoT);
    cudaGetSymbolAddress((void**)&W1T, g_W1T);
    cudaGetSymbolAddress((void**)&W2T, g_W2T);
    cudaGetSymbolAddress((void**)&cphh, g_cph16);
    cudaGetSymbolAddress((void**)&sphh, g_sph16);
    cudaGetSymbolAddress((void**)&maskhp, g_mask16);

    const int smG = 4 * 2 * TILE_B;           // 81920
    cudaFuncSetAttribute(flash_kernel, cudaFuncAttributeMaxDynamicSharedMemorySize, FLASH_SMEM);
    cudaFuncSetAttribute((const void*)tgemm_kernel<4>, cudaFuncAttributeMaxDynamicSharedMemorySize, smG);

    // weights transpose + h->fp16 + mask, one launch
    wtrans_all_kernel<<<3585, dim3(32, 8)>>>(Wq, Wk, Wv, Wo, W1, W2, h, mask,
                                             WqkvT, WoT, W1T, W2T, h16, maskhp);

    // fused QKV projection -> fp16 (Q cols scaled by log2e/16)
    tgemm_kernel<4><<<dim3(QKVS / 128, ROWS / 128), 256, smG>>>(
        h16, WqkvT, nullptr, nullptr, QKVh, Dq, QKVS, 8 | 16);
    proj8_kernel<<<ROWS / 32, 256>>>(h, Wp, bp, nullptr, nullptr, cphh, sphh, 0);

    // fused flash attention
    flash_kernel<<<dim3(Nq / 128, BHq), 256, FLASH_SMEM>>>(QKVh, cphh, sphh, maskhp, mh);

    // Wo projection (fp16 -> fp32)
    tgemm_kernel<4><<<dim3(Dq / 128, ROWS / 128), 256, smG>>>(
        mh, WoT, nullptr, msgO, nullptr, Dq, Dq, 0);
    addln_kernel<<<ROWS / 8, 256>>>(h, msgO, g1, be1, h1, h1h, nullptr, nullptr);

    // FFN (fp16)
    tgemm_kernel<4><<<dim3(Fq / 128, ROWS / 128), 256, smG>>>(
        h1h, W1T, b1, nullptr, f1h, Dq, Fq, 11);
    tgemm_kernel<4><<<dim3(Dq / 128, ROWS / 128), 256, smG>>>(
        f1h, W2T, b2, ffn2, nullptr, Fq, Dq, 1);
    addln_kernel<<<ROWS / 8, 256>>>(h1, ffn2, g2, be2, out_h2, nullptr, h, rn);

    // phase update + delta
    proj8_kernel<<<ROWS / 32, 256>>>(out_h2, Wph, bph, phases, out_phases, nullptr, nullptr, 1);
    delta_kernel<<<1, 256>>>(rn, out_delta);
}

// round 14
// speedup vs baseline: 1.1865x; 1.0948x over previous
#include <cuda_runtime.h>
#include <cuda_bf16.h>
#include <cuda_fp16.h>
#include <math.h>
#include <stdint.h>

#define Bq 2
#define Nq 2048
#define Dq 512
#define Hq 8
#define Fq 2048
#define DHq 64
#define ROWS (Bq*Nq)            // 4096
#define BHq (Bq*Hq)             // 16
#define QKVS (3*Dq)             // 1536
#define QSCL 0.0901684403f      // (1/16) * log2(e)

// ---------------- scratch (static device globals) ---------------------------
__device__ float g_msgO[ROWS*Dq];
__device__ float g_h1[ROWS*Dq];
__device__ float g_ffn2[ROWS*Dq];
__device__ float g_rn[ROWS];

__device__ __half g_QKVh[(size_t)ROWS*QKVS];
__device__ __half g_h16[ROWS*Dq];
__device__ __half g_mh[ROWS*Dq];
__device__ __half g_h1h[ROWS*Dq];
__device__ __half g_ffn1h[(size_t)ROWS*Fq];
__device__ __half g_WqkvT[3*Dq*Dq];
__device__ __half g_WoT[Dq*Dq];
__device__ __half g_W1T[(size_t)Fq*Dq];
__device__ __half g_W2T[(size_t)Dq*Fq];
__device__ __half g_cph16[BHq*Nq];
__device__ __half g_sph16[BHq*Nq];
__device__ __half g_mask16[Bq*Nq];

// ---------------- PTX helpers -----------------------------------------------
__device__ __forceinline__ uint32_t smem_u32(const void* p) {
    return (uint32_t)__cvta_generic_to_shared(p);
}
__device__ __forceinline__ void cp16(uint32_t s, const void* g) {
    asm volatile("cp.async.cg.shared.global [%0], [%1], 16;" :: "r"(s), "l"(g));
}
__device__ __forceinline__ void cp_commit() { asm volatile("cp.async.commit_group;" ::: "memory"); }
__device__ __forceinline__ void cp_wait1()  { asm volatile("cp.async.wait_group 1;" ::: "memory"); }

__device__ __forceinline__ void ldm_x4(uint32_t* r, uint32_t addr) {
    asm volatile("ldmatrix.sync.aligned.m8n8.x4.shared.b16 {%0,%1,%2,%3}, [%4];"
                 : "=r"(r[0]), "=r"(r[1]), "=r"(r[2]), "=r"(r[3]) : "r"(addr));
}
__device__ __forceinline__ void ldm_x4_t(uint32_t* r, uint32_t addr) {
    asm volatile("ldmatrix.sync.aligned.m8n8.x4.trans.shared.b16 {%0,%1,%2,%3}, [%4];"
                 : "=r"(r[0]), "=r"(r[1]), "=r"(r[2]), "=r"(r[3]) : "r"(addr));
}
__device__ __forceinline__ void mma16816h(float* c, const uint32_t* a, const uint32_t* b) {
    asm volatile("mma.sync.aligned.m16n8k16.row.col.f32.f16.f16.f32 "
                 "{%0,%1,%2,%3}, {%4,%5,%6,%7}, {%8,%9}, {%0,%1,%2,%3};"
                 : "+f"(c[0]), "+f"(c[1]), "+f"(c[2]), "+f"(c[3])
                 : "r"(a[0]), "r"(a[1]), "r"(a[2]), "r"(a[3]), "r"(b[0]), "r"(b[1]));
}
__device__ __forceinline__ void mma16816hh(uint32_t* c, const uint32_t* a, const uint32_t* b) {
    asm volatile("mma.sync.aligned.m16n8k16.row.col.f16.f16.f16.f16 "
                 "{%0,%1}, {%2,%3,%4,%5}, {%6,%7}, {%0,%1};"
                 : "+r"(c[0]), "+r"(c[1])
                 : "r"(a[0]), "r"(a[1]), "r"(a[2]), "r"(a[3]), "r"(b[0]), "r"(b[1]));
}
__device__ __forceinline__ uint32_t ex2h2(__half2 s) {
    uint32_t r;
    asm("ex2.approx.f16x2 %0, %1;" : "=r"(r) : "r"(*(uint32_t*)&s));
    return r;
}

// ---------------- HMMA fp16 GEMM: C = A(MxK) @ BT(NxK)^T ---------------------
// epi bit0: +bias ; bit1: GELU ; bit3: fp16 out ; bit4: scale cols<Dq by QSCL
#define TSTR 40
#define TILE_B (128 * TSTR * 2)         // 10240 bytes per tile
template<int STAGES>
__global__ __launch_bounds__(256, 2) void tgemm_kernel(
    const __half* __restrict__ A, const __half* __restrict__ B,
    const float* __restrict__ bias,
    float* __restrict__ Cf, __half* __restrict__ C16,
    int K, int Nc, int epi)
{
    extern __shared__ __align__(128) unsigned char dsm[];
    const uint32_t stg = 2 * TILE_B;
    const uint32_t sb = smem_u32(dsm);
    const int tid = threadIdx.x;
    const int warp = tid >> 5, lane = tid & 31;
    const int wm = warp >> 1, wn = warp & 1;
    const int bm = blockIdx.y * 128, bn = blockIdx.x * 128;

    const int NCH = K >> 5;
    const int lrow = tid >> 2, lch = (tid & 3) << 3;

    float acc[2][8][4];
    #pragma unroll
    for (int i = 0; i < 2; i++)
        #pragma unroll
        for (int j = 0; j < 8; j++)
            #pragma unroll
            for (int q = 0; q < 4; q++) acc[i][j][q] = 0.f;

    auto issue = [&](int c) {
        if (c < NCH) {
            const int kc = c << 5;
            const uint32_t base = sb + (uint32_t)(c % STAGES) * stg;
            #pragma unroll
            for (int i = 0; i < 2; i++) {
                const int row = lrow + i * 64;
                const uint32_t so = (uint32_t)(row * TSTR + lch) * 2;
                cp16(base + so,          A + (size_t)(bm + row) * K + kc + lch);
                cp16(base + TILE_B + so, B + (size_t)(bn + row) * K + kc + lch);
            }
        }
        cp_commit();
    };

    #pragma unroll
    for (int p = 0; p < STAGES - 1; p++) issue(p);

    for (int c = 0; c < NCH; c++) {
        asm volatile("cp.async.wait_group %0;" :: "n"(STAGES - 2));
        __syncthreads();
        issue(c + STAGES - 1);
        const uint32_t base = sb + (uint32_t)(c % STAGES) * stg;
        #pragma unroll
        for (int ks = 0; ks < 2; ks++) {
            const uint32_t arow = (uint32_t)((wm * 32 + (lane & 15)) * TSTR
                                             + ks * 16 + ((lane >> 4) << 3)) * 2;
            const uint32_t brow = (uint32_t)((wn * 64 + ((lane >> 4) << 3) + (lane & 7)) * TSTR
                                             + ks * 16 + (((lane >> 3) & 1) << 3)) * 2;
            uint32_t aH[2][4], bH[4][4];
            #pragma unroll
            for (int mt = 0; mt < 2; mt++)
                ldm_x4(aH[mt], base + arow + (uint32_t)(mt * 16 * TSTR) * 2);
            #pragma unroll
            for (int nt4 = 0; nt4 < 4; nt4++)
                ldm_x4(bH[nt4], base + TILE_B + brow + (uint32_t)(nt4 * 16 * TSTR) * 2);
            #pragma unroll
            for (int mt = 0; mt < 2; mt++)
                #pragma unroll
                for (int nt = 0; nt < 8; nt++)
                    mma16816h(acc[mt][nt], aH[mt], &bH[nt >> 1][(nt & 1) * 2]);
        }
        __syncthreads();
    }

    #pragma unroll
    for (int mt = 0; mt < 2; mt++) {
        const int r0 = bm + wm * 32 + mt * 16 + (lane >> 2);
        #pragma unroll
        for (int nt = 0; nt < 8; nt++) {
            const int gn = bn + wn * 64 + nt * 8 + ((lane & 3) << 1);
            #pragma unroll
            for (int half = 0; half < 2; half++) {
                const int row = r0 + half * 8;
                float v0 = acc[mt][nt][half * 2 + 0];
                float v1 = acc[mt][nt][half * 2 + 1];
                if (epi & 1) { v0 += bias[gn]; v1 += bias[gn + 1]; }
                if (epi & 2) {
                    v0 = 0.5f * v0 * (1.f + erff(v0 * 0.7071067811865475f));
                    v1 = 0.5f * v1 * (1.f + erff(v1 * 0.7071067811865475f));
                }
                if ((epi & 16) && gn < Dq) { v0 *= QSCL; v1 *= QSCL; }
                const size_t idx = (size_t)row * Nc + gn;
                if (epi & 8) {
                    *(__half2*)(C16 + idx) = __floats2half2_rn(v0, v1);
                } else {
                    *(float2*)(Cf + idx) = make_float2(v0, v1);
                }
            }
        }
    }
}

// ---------------- fused flash attention (fp16 acc, half2 harmonic) -----------
#define FLASH_STAGE 37632
#define FLASH_Q     18432
#define FLASH_SMEM  (FLASH_Q + 2 * FLASH_STAGE)     // 93696
__global__ __launch_bounds__(256, 2) void flash_kernel(
    const __half* __restrict__ QKV,
    const __half* __restrict__ cph, const __half* __restrict__ sph,
    const __half* __restrict__ maskh,
    __half* __restrict__ Mh)
{
    extern __shared__ __align__(128) unsigned char fsm[];
    const int tid = threadIdx.x, warp = tid >> 5, lane = tid & 31;
    const int wq = warp & 3, wn = warp >> 2;
    const int bh = blockIdx.y, b = bh >> 3, hh = bh & 7;
    const int n0 = blockIdx.x * 128;
    const uint32_t sb = smem_u32(fsm);

    const __half* gQ = QKV + ((size_t)b * Nq + n0) * QKVS + hh * DHq;
    #pragma unroll
    for (int i = 0; i < 4; i++) {
        const int id = tid + i * 256, row = id >> 3, ch = id & 7;
        cp16(sb + row * 144 + ch * 16, gQ + (size_t)row * QKVS + ch * 8);
    }
    cp_commit();

    auto issueKV = [&](int step, int s) {
        const uint32_t ku = sb + FLASH_Q + s * FLASH_STAGE;
        const uint32_t vu = ku + 18432, cku = ku + 36864, sku = ku + 37120, mku = ku + 37376;
        const __half* gK = QKV + ((size_t)b * Nq + step * 128) * QKVS + Dq + hh * DHq;
        const __half* gV = gK + Dq;
        #pragma unroll
        for (int i = 0; i < 4; i++) {
            const int id = tid + i * 256, row = id >> 3, ch = id & 7;
            cp16(ku + row * 144 + ch * 16, gK + (size_t)row * QKVS + ch * 8);
            cp16(vu + row * 144 + ch * 16, gV + (size_t)row * QKVS + ch * 8);
        }
        if (tid < 16)      cp16(cku + tid * 16, cph + (size_t)bh * Nq + step * 128 + tid * 8);
        else if (tid < 32) cp16(sku + (tid - 16) * 16, sph + (size_t)bh * Nq + step * 128 + (tid - 16) * 8);
        else if (tid < 48) cp16(mku + (tid - 32) * 16, maskh + (size_t)b * Nq + step * 128 + (tid - 32) * 8);
        cp_commit();
    };
    issueKV(0, 0);
    issueKV(1, 1);
    cp_wait1();
    __syncthreads();

    const int qbase = wq * 32, r = lane >> 2;
    uint32_t qf[2][4][4];
    #pragma unroll
    for (int t = 0; t < 2; t++)
        #pragma unroll
        for (int kc = 0; kc < 4; kc++)
            ldm_x4(qf[t][kc], sb + (uint32_t)((qbase + t * 16 + (lane & 15)) * 144
                                              + (kc * 16 + ((lane >> 4) << 3)) * 2));
    const __half2 cqA = __half2half2(cph[(size_t)bh * Nq + n0 + qbase + r]);
    const __half2 sqA = __half2half2(sph[(size_t)bh * Nq + n0 + qbase + r]);
    const __half2 cqB = __half2half2(cph[(size_t)bh * Nq + n0 + qbase + r + 8]);
    const __half2 sqB = __half2half2(sph[(size_t)bh * Nq + n0 + qbase + r + 8]);
    const __half2 cqC = __half2half2(cph[(size_t)bh * Nq + n0 + qbase + 16 + r]);
    const __half2 sqC = __half2half2(sph[(size_t)bh * Nq + n0 + qbase + 16 + r]);
    const __half2 cqD = __half2half2(cph[(size_t)bh * Nq + n0 + qbase + 16 + r + 8]);
    const __half2 sqD = __half2half2(sph[(size_t)bh * Nq + n0 + qbase + 16 + r + 8]);

    uint32_t O[2][8][2];
    #pragma unroll
    for (int t = 0; t < 2; t++)
        #pragma unroll
        for (int i = 0; i < 8; i++) { O[t][i][0] = 0u; O[t][i][1] = 0u; }
    float l[4] = {0.f, 0.f, 0.f, 0.f};

    const int NSTEP = Nq / 128;
    for (int c = 0; c < NSTEP; c++) {
        if (c > 0) { cp_wait1(); __syncthreads(); }
        const uint32_t ku = sb + FLASH_Q + (c & 1) * FLASH_STAGE;
        const uint32_t vu = ku + 18432;
        const __half* ckh = (const __half*)(fsm + FLASH_Q + (c & 1) * FLASH_STAGE + 36864);
        const __half* skh = ckh + 128;
        const __half* mkh = skh + 128;

        uint32_t c0[8][2], c1[8][2];
        #pragma unroll
        for (int g = 0; g < 8; g++) {
            c0[g][0] = 0u; c0[g][1] = 0u; c1[g][0] = 0u; c1[g][1] = 0u;
        }

        #pragma unroll
        for (int kc = 0; kc < 4; kc++) {
            #pragma unroll
            for (int gp = 0; gp < 4; gp++) {
                uint32_t bb[4];
                const int krow = wn * 64 + gp * 16 + ((lane >> 4) << 3) + (lane & 7);
                ldm_x4(bb, ku + (uint32_t)(krow * 144 + (kc * 16 + (((lane >> 3) & 1) << 3)) * 2));
                mma16816hh(c0[2 * gp],     qf[0][kc], bb);
                mma16816hh(c0[2 * gp + 1], qf[0][kc], bb + 2);
                mma16816hh(c1[2 * gp],     qf[1][kc], bb);
                mma16816hh(c1[2 * gp + 1], qf[1][kc], bb + 2);
            }
        }

        __half2 L0 = __floats2half2_rn(0.f, 0.f), L1 = L0, L2 = L0, L3 = L0;
        #pragma unroll
        for (int g = 0; g < 8; g++) {
            const int kg = wn * 64 + g * 8 + ((lane & 3) << 1);
            const __half2 ck2 = *(const __half2*)(ckh + kg);
            const __half2 sk2 = *(const __half2*)(skh + kg);
            const __half2 mk2 = *(const __half2*)(mkh + kg);
            {
                const __half2 cv = *(__half2*)&c0[g][0];
                const __half2 hx = __hfma2(sqA, sk2, __hmul2(cqA, ck2));
                const uint32_t p = ex2h2(__hadd2(__hfma2(cv, hx, cv), mk2));
                c0[g][0] = p;
                L0 = __hadd2(L0, *(__half2*)&p);
            }
            {
                const __half2 cv = *(__half2*)&c0[g][1];
                const __half2 hx = __hfma2(sqB, sk2, __hmul2(cqB, ck2));
                const uint32_t p = ex2h2(__hadd2(__hfma2(cv, hx, cv), mk2));
                c0[g][1] = p;
                L1 = __hadd2(L1, *(__half2*)&p);
            }
            {
                const __half2 cv = *(__half2*)&c1[g][0];
                const __half2 hx = __hfma2(sqC, sk2, __hmul2(cqC, ck2));
                const uint32_t p = ex2h2(__hadd2(__hfma2(cv, hx, cv), mk2));
                c1[g][0] = p;
                L2 = __hadd2(L2, *(__half2*)&p);
            }
            {
                const __half2 cv = *(__half2*)&c1[g][1];
                const __half2 hx = __hfma2(sqD, sk2, __hmul2(cqD, ck2));
                const uint32_t p = ex2h2(__hadd2(__hfma2(cv, hx, cv), mk2));
                c1[g][1] = p;
                L3 = __hadd2(L3, *(__half2*)&p);
            }
        }
        l[0] += __low2float(L0) + __high2float(L0);
        l[1] += __low2float(L1) + __high2float(L1);
        l[2] += __low2float(L2) + __high2float(L2);
        l[3] += __low2float(L3) + __high2float(L3);

        #pragma unroll
        for (int kc2 = 0; kc2 < 4; kc2++) {
            uint32_t aA[4], aB[4];
            aA[0] = c0[2 * kc2][0];     aA[1] = c0[2 * kc2][1];
            aA[2] = c0[2 * kc2 + 1][0]; aA[3] = c0[2 * kc2 + 1][1];
            aB[0] = c1[2 * kc2][0];     aB[1] = c1[2 * kc2][1];
            aB[2] = c1[2 * kc2 + 1][0]; aB[3] = c1[2 * kc2 + 1][1];
            const int vrow = wn * 64 + kc2 * 16 + (lane & 15);
            #pragma unroll
            for (int dgp = 0; dgp < 4; dgp++) {
                uint32_t bb[4];
                ldm_x4_t(bb, vu + (uint32_t)(vrow * 144 + (dgp * 16 + ((lane >> 4) << 3)) * 2));
                mma16816hh(O[0][2 * dgp],     aA, bb);
                mma16816hh(O[0][2 * dgp + 1], aA, bb + 2);
                mma16816hh(O[1][2 * dgp],     aB, bb);
                mma16816hh(O[1][2 * dgp + 1], aB, bb + 2);
            }
        }
        __syncthreads();
        if (c + 2 < NSTEP) issueKV(c + 2, c & 1);
    }

    #pragma unroll
    for (int i = 0; i < 4; i++) {
        l[i] += __shfl_xor_sync(~0u, l[i], 1);
        l[i] += __shfl_xor_sync(~0u, l[i], 2);
    }

    float* redO = (float*)fsm;                       // [128][66]
    float* redL = (float*)(fsm + 128 * 66 * 4);      // [128]
    if (wn == 1) {
        #pragma unroll
        for (int t = 0; t < 2; t++) {
            const int row0 = qbase + t * 16 + r, row1 = row0 + 8;
            #pragma unroll
            for (int dg = 0; dg < 8; dg++) {
                const int col = dg * 8 + ((lane & 3) << 1);
                const float2 a0 = __half22float2(*(__half2*)&O[t][dg][0]);
                const float2 a1 = __half22float2(*(__half2*)&O[t][dg][1]);
                redO[row0 * 66 + col]     = a0.x;
                redO[row0 * 66 + col + 1] = a0.y;
                redO[row1 * 66 + col]     = a1.x;
                redO[row1 * 66 + col + 1] = a1.y;
            }
            if ((lane & 3) == 0) { redL[row0] = l[2 * t]; redL[row1] = l[2 * t + 1]; }
        }
    }
    __syncthreads();
    if (wn == 0) {
        #pragma unroll
        for (int t = 0; t < 2; t++) {
            const int row0 = qbase + t * 16 + r, row1 = row0 + 8;
            const float i0 = 1.f / (l[2 * t] + redL[row0]);
            const float i1 = 1.f / (l[2 * t + 1] + redL[row1]);
            const size_t gr0 = (size_t)(b * Nq + n0 + row0) * Dq + hh * DHq;
            const size_t gr1 = (size_t)(b * Nq + n0 + row1) * Dq + hh * DHq;
            #pragma unroll
            for (int dg = 0; dg < 8; dg++) {
                const int col = dg * 8 + ((lane & 3) << 1);
                const float2 a0 = __half22float2(*(__half2*)&O[t][dg][0]);
                const float2 a1 = __half22float2(*(__half2*)&O[t][dg][1]);
                *(__half2*)(Mh + gr0 + col) =
                    __floats2half2_rn((a0.x + redO[row0 * 66 + col]) * i0,
                                      (a0.y + redO[row0 * 66 + col + 1]) * i0);
                *(__half2*)(Mh + gr1 + col) =
                    __floats2half2_rn((a1.x + redO[row1 * 66 + col]) * i1,
                                      (a1.y + redO[row1 * 66 + col + 1]) * i1);
            }
        }
    }
}

// ---------------- fused weight transpose + h convert + mask (one launch) -----
__device__ __forceinline__ void wtile_h(const float* __restrict__ W, __half* __restrict__ T,
                                        int K, int Nc, int k0, int n0, int tx, int ty,
                                        float t[32][33]) {
    #pragma unroll
    for (int i = ty; i < 32; i += 8) t[i][tx] = W[(size_t)(k0 + i) * Nc + n0 + tx];
    __syncthreads();
    #pragma unroll
    for (int i = ty; i < 32; i += 8)
        T[(size_t)(n0 + i) * K + k0 + tx] = __float2half_rn(t[tx][i]);
}

__global__ void wtrans_all_kernel(
    const float* Wq, const float* Wk, const float* Wv, const float* Wo,
    const float* W1, const float* W2, const float* h, const unsigned char* mask,
    __half* qkvT, __half* oT, __half* w1T, __half* w2T, __half* h16, __half* maskh)
{
    __shared__ float t[32][33];
    const int tx = threadIdx.x, ty = threadIdx.y;
    const int tid = ty * 32 + tx;
    int id = blockIdx.x;
    if (id < 1024) {
        const int w = id >> 8, tl = id & 255;
        const int n0 = (tl & 15) * 32, k0 = (tl >> 4) * 32;
        const float* W = (w == 0) ? Wq : (w == 1) ? Wk : (w == 2) ? Wv : Wo;
        __half* T = (w < 3) ? (qkvT + (size_t)w * Dq * Dq) : oT;
        wtile_h(W, T, Dq, Dq, k0, n0, tx, ty, t);
    } else if (id < 2048) {
        const int tl = id - 1024;
        wtile_h(W1, w1T, Dq, Fq, (tl >> 6) * 32, (tl & 63) * 32, tx, ty, t);
    } else if (id < 3072) {
        const int tl = id - 2048;
        wtile_h(W2, w2T, Fq, Dq, (tl >> 4) * 32, (tl & 15) * 32, tx, ty, t);
    } else if (id < 3584) {
        const size_t base = (size_t)(id - 3072) * 4096 + tid * 16;
        #pragma unroll
        for (int i = 0; i < 4; i++) {
            const float4 v = *(const float4*)(h + base + i * 4);
            *(__half2*)(h16 + base + i * 4)     = __floats2half2_rn(v.x, v.y);
            *(__half2*)(h16 + base + i * 4 + 2) = __floats2half2_rn(v.z, v.w);
        }
    } else {
        for (int i = tid; i < Bq * Nq; i += 256)
            maskh[i] = __float2half(mask[i] ? -100.f : 0.f);
    }
}

// ---------------- 8-wide projection: cos/sin (mode0) / phases+delta (mode1) --
__global__ __launch_bounds__(256) void proj8_kernel(
    const float* __restrict__ X, const float* __restrict__ W8,
    const float* __restrict__ b8, const float* __restrict__ phases,
    float* __restrict__ out, __half* __restrict__ cph, __half* __restrict__ sph,
    const float* __restrict__ rn, float* __restrict__ out_delta, int mode)
{
    if (mode && blockIdx.x == ROWS / 32) {
        __shared__ float red[256];
        const int tid = threadIdx.x;
        float s = 0.f;
        for (int i = tid; i < ROWS; i += 256) s += rn[i];
        red[tid] = s; __syncthreads();
        #pragma unroll
        for (int o = 128; o; o >>= 1) { if (tid < o) red[tid] += red[tid + o]; __syncthreads(); }
        if (tid == 0) out_delta[0] = red[0] * (1.f / ROWS);
        return;
    }
    __shared__ float w8t[8][516];
    __shared__ float b8s[8];
    const int tid = threadIdx.x;
    for (int i = tid; i < Dq * Hq; i += 256) w8t[i & 7][i >> 3] = W8[i];
    if (tid < 8) b8s[tid] = b8[tid];
    __syncthreads();
    const int warp = tid >> 5, lane = tid & 31;
    #pragma unroll
    for (int rr = 0; rr < 4; rr++) {
        const int row = blockIdx.x * 32 + warp * 4 + rr;
        const float4* X4 = (const float4*)(X + (size_t)row * Dq);
        float acc[8] = {0.f, 0.f, 0.f, 0.f, 0.f, 0.f, 0.f, 0.f};
        #pragma unroll
        for (int i = 0; i < 4; i++) {
            const int c4 = lane + i * 32;
            const float4 xv = X4[c4];
            #pragma unroll
            for (int w = 0; w < 8; w++) {
                const float4 wv = ((const float4*)&w8t[w][0])[c4];
                acc[w] += xv.x * wv.x + xv.y * wv.y + xv.z * wv.z + xv.w * wv.w;
            }
        }
        #pragma unroll
        for (int w = 0; w < 8; w++)
            #pragma unroll
            for (int o = 16; o; o >>= 1) acc[w] += __shfl_xor_sync(~0u, acc[w], o);
        if (lane < 8) {
            float s = b8s[lane];
            #pragma unroll
            for (int w = 0; w < 8; w++) if (lane == w) s += acc[w];
            if (mode) {
                out[(size_t)row * Hq + lane] = phases[(size_t)row * Hq + lane]
                                               + 0.31415926535897932f * tanhf(s);
            } else {
                const int b = row >> 11, n = row & 2047;
                cph[(size_t)(b * Hq + lane) * Nq + n] = __float2half(cosf(s));
                sph[(size_t)(b * Hq + lane) * Nq + n] = __float2half(sinf(s));
            }
        }
    }
}

// ---------------- residual add + LayerNorm (warp per row) --------------------
__global__ __launch_bounds__(256) void addln_kernel(
    const float* __restrict__ X, const float* __restrict__ Y,
    const float* __restrict__ g, const float* __restrict__ be,
    float* __restrict__ out, __half* __restrict__ oh16,
    const float* __restrict__ href, float* __restrict__ rn)
{
    const int warp = threadIdx.x >> 5, lane = threadIdx.x & 31;
    const size_t row = blockIdx.x * 8 + warp;
    const float4* X4 = (const float4*)(X + row * Dq);
    const float4* Y4 = (const float4*)(Y + row * Dq);
    float a[16];
    float s = 0.f;
    #pragma unroll
    for (int i = 0; i < 4; i++) {
        const float4 xv = X4[lane + i * 32];
        const float4 yv = Y4[lane + i * 32];
        a[4 * i + 0] = xv.x + yv.x; a[4 * i + 1] = xv.y + yv.y;
        a[4 * i + 2] = xv.z + yv.z; a[4 * i + 3] = xv.w + yv.w;
        s += a[4 * i] + a[4 * i + 1] + a[4 * i + 2] + a[4 * i + 3];
    }
    #pragma unroll
    for (int o = 16; o; o >>= 1) s += __shfl_xor_sync(~0u, s, o);
    const float mu = s * (1.f / Dq);
    float vs = 0.f;
    #pragma unroll
    for (int i = 0; i < 16; i++) { const float d = a[i] - mu; vs += d * d; }
    #pragma unroll
    for (int o = 16; o; o >>= 1) vs += __shfl_xor_sync(~0u, vs, o);
    const float rstd = rsqrtf(vs * (1.f / Dq) + 1e-5f);
    float ss = 0.f;
    #pragma unroll
    for (int i = 0; i < 4; i++) {
        const int c4 = lane + i * 32;
        const float4 gv = ((const float4*)g)[c4];
        const float4 bv = ((const float4*)be)[c4];
        float4 r;
        r.x = (a[4 * i + 0] - mu) * rstd * gv.x + bv.x;
        r.y = (a[4 * i + 1] - mu) * rstd * gv.y + bv.y;
        r.z = (a[4 * i + 2] - mu) * rstd * gv.z + bv.z;
        r.w = (a[4 * i + 3] - mu) * rstd * gv.w + bv.w;
        ((float4*)(out + row * Dq))[c4] = r;
        if (oh16) {
            *(__half2*)(oh16 + row * Dq + c4 * 4)     = __floats2half2_rn(r.x, r.y);
            *(__half2*)(oh16 + row * Dq + c4 * 4 + 2) = __floats2half2_rn(r.z, r.w);
        }
        if (href) {
            const float4 hv = ((const float4*)(href + row * Dq))[c4];
            const float d0 = r.x - hv.x, d1 = r.y - hv.y, d2 = r.z - hv.z, d3 = r.w - hv.w;
            ss += d0 * d0 + d1 * d1 + d2 * d2 + d3 * d3;
        }
    }
    if (href) {
        #pragma unroll
        for (int o = 16; o; o >>= 1) ss += __shfl_xor_sync(~0u, ss, o);
        if (lane == 0) rn[row] = sqrtf(ss);
    }
}

// ---------------- launch ------------------------------------------------------
extern "C" void kernel_launch(void* const* d_in, const int* in_sizes, int n_in,
                              void* d_out, int out_size) {
    const float* h      = (const float*)d_in[0];
    const float* phases = (const float*)d_in[1];
    const unsigned char* mask = (const unsigned char*)d_in[2];
    const float* Wq  = (const float*)d_in[3];
    const float* Wk  = (const float*)d_in[4];
    const float* Wp  = (const float*)d_in[5];
    const float* bp  = (const float*)d_in[6];
    const float* Wv  = (const float*)d_in[7];
    const float* Wo  = (const float*)d_in[8];
    const float* W1  = (const float*)d_in[9];
    const float* b1  = (const float*)d_in[10];
    const float* W2  = (const float*)d_in[11];
    const float* b2  = (const float*)d_in[12];
    const float* g1  = (const float*)d_in[13];
    const float* be1 = (const float*)d_in[14];
    const float* g2  = (const float*)d_in[15];
    const float* be2 = (const float*)d_in[16];
    const float* Wph = (const float*)d_in[17];
    const float* bph = (const float*)d_in[18];

    float* out_h2     = (float*)d_out;
    float* out_phases = out_h2 + (size_t)ROWS * Dq;
    float* out_delta  = out_phases + (size_t)ROWS * Hq;

    float *msgO, *h1, *ffn2, *rn;
    __half *QKVh, *h16, *mh, *h1h, *f1h, *WqkvT, *WoT, *W1T, *W2T, *cphh, *sphh, *maskhp;
    cudaGetSymbolAddress((void**)&msgO, g_msgO);
    cudaGetSymbolAddress((void**)&h1, g_h1);    cudaGetSymbolAddress((void**)&ffn2, g_ffn2);
    cudaGetSymbolAddress((void**)&rn, g_rn);
    cudaGetSymbolAddress((void**)&QKVh, g_QKVh);
    cudaGetSymbolAddress((void**)&h16, g_h16);
    cudaGetSymbolAddress((void**)&mh, g_mh);
    cudaGetSymbolAddress((void**)&h1h, g_h1h);
    cudaGetSymbolAddress((void**)&f1h, g_ffn1h);
    cudaGetSymbolAddress((void**)&WqkvT, g_WqkvT);
    cudaGetSymbolAddress((void**)&WoT, g_WoT);
    cudaGetSymbolAddress((void**)&W1T, g_W1T);
    cudaGetSymbolAddress((void**)&W2T, g_W2T);
    cudaGetSymbolAddress((void**)&cphh, g_cph16);
    cudaGetSymbolAddress((void**)&sphh, g_sph16);
    cudaGetSymbolAddress((void**)&maskhp, g_mask16);

    const int smG = 4 * 2 * TILE_B;           // 81920
    cudaFuncSetAttribute(flash_kernel, cudaFuncAttributeMaxDynamicSharedMemorySize, FLASH_SMEM);
    cudaFuncSetAttribute((const void*)tgemm_kernel<4>, cudaFuncAttributeMaxDynamicSharedMemorySize, smG);

    // weights transpose + h->fp16 + mask, one launch
    wtrans_all_kernel<<<3585, dim3(32, 8)>>>(Wq, Wk, Wv, Wo, W1, W2, h, mask,
                                             WqkvT, WoT, W1T, W2T, h16, maskhp);

    // fused QKV projection -> fp16 (Q cols scaled by log2e/16)
    tgemm_kernel<4><<<dim3(QKVS / 128, ROWS / 128), 256, smG>>>(
        h16, WqkvT, nullptr, nullptr, QKVh, Dq, QKVS, 8 | 16);
    proj8_kernel<<<ROWS / 32, 256>>>(h, Wp, bp, nullptr, nullptr, cphh, sphh, nullptr, nullptr, 0);

    // fused flash attention
    flash_kernel<<<dim3(Nq / 128, BHq), 256, FLASH_SMEM>>>(QKVh, cphh, sphh, maskhp, mh);

    // Wo projection (fp16 -> fp32)
    tgemm_kernel<4><<<dim3(Dq / 128, ROWS / 128), 256, smG>>>(
        mh, WoT, nullptr, msgO, nullptr, Dq, Dq, 0);
    addln_kernel<<<ROWS / 8, 256>>>(h, msgO, g1, be1, h1, h1h, nullptr, nullptr);

    // FFN (fp16)
    tgemm_kernel<4><<<dim3(Fq / 128, ROWS / 128), 256, smG>>>(
        h1h, W1T, b1, nullptr, f1h, Dq, Fq, 11);
    tgemm_kernel<4><<<dim3(Dq / 128, ROWS / 128), 256, smG>>>(
        f1h, W2T, b2, ffn2, nullptr, Fq, Dq, 1);
    addln_kernel<<<ROWS / 8, 256>>>(h1, ffn2, g2, be2, out_h2, nullptr, h, rn);

    // phase update + delta (one launch)
    proj8_kernel<<<ROWS / 32 + 1, 256>>>(out_h2, Wph, bph, phases, out_phases,
                                         nullptr, nullptr, rn, out_delta, 1);
}

// round 15
// speedup vs baseline: 1.2002x; 1.0116x over previous
#include <cuda_runtime.h>
#include <cuda_bf16.h>
#include <cuda_fp16.h>
#include <math.h>
#include <stdint.h>

#define Bq 2
#define Nq 2048
#define Dq 512
#define Hq 8
#define Fq 2048
#define DHq 64
#define ROWS (Bq*Nq)            // 4096
#define BHq (Bq*Hq)             // 16
#define QKVS (3*Dq)             // 1536
#define QSCL 0.0901684403f      // (1/16) * log2(e)

// ---------------- scratch (static device globals) ---------------------------
__device__ float g_msgO[ROWS*Dq];
__device__ float g_h1[ROWS*Dq];
__device__ float g_ffn2[ROWS*Dq];
__device__ float g_rn[ROWS];

__device__ __half g_QKVh[(size_t)ROWS*QKVS];
__device__ __half g_h16[ROWS*Dq];
__device__ __half g_mh[ROWS*Dq];
__device__ __half g_h1h[ROWS*Dq];
__device__ __half g_ffn1h[(size_t)ROWS*Fq];
__device__ __half g_WqkvT[3*Dq*Dq];
__device__ __half g_WoT[Dq*Dq];
__device__ __half g_W1T[(size_t)Fq*Dq];
__device__ __half g_W2T[(size_t)Dq*Fq];
__device__ __half g_cph16[BHq*Nq];
__device__ __half g_sph16[BHq*Nq];
__device__ __half g_mask16[Bq*Nq];

// ---------------- PTX helpers -----------------------------------------------
__device__ __forceinline__ uint32_t smem_u32(const void* p) {
    return (uint32_t)__cvta_generic_to_shared(p);
}
__device__ __forceinline__ void cp16(uint32_t s, const void* g) {
    asm volatile("cp.async.cg.shared.global [%0], [%1], 16;" :: "r"(s), "l"(g));
}
__device__ __forceinline__ void cp_commit() { asm volatile("cp.async.commit_group;" ::: "memory"); }
__device__ __forceinline__ void cp_wait1()  { asm volatile("cp.async.wait_group 1;" ::: "memory"); }

__device__ __forceinline__ void ldm_x4(uint32_t* r, uint32_t addr) {
    asm volatile("ldmatrix.sync.aligned.m8n8.x4.shared.b16 {%0,%1,%2,%3}, [%4];"
                 : "=r"(r[0]), "=r"(r[1]), "=r"(r[2]), "=r"(r[3]) : "r"(addr));
}
__device__ __forceinline__ void ldm_x4_t(uint32_t* r, uint32_t addr) {
    asm volatile("ldmatrix.sync.aligned.m8n8.x4.trans.shared.b16 {%0,%1,%2,%3}, [%4];"
                 : "=r"(r[0]), "=r"(r[1]), "=r"(r[2]), "=r"(r[3]) : "r"(addr));
}
__device__ __forceinline__ void mma16816h(float* c, const uint32_t* a, const uint32_t* b) {
    asm volatile("mma.sync.aligned.m16n8k16.row.col.f32.f16.f16.f32 "
                 "{%0,%1,%2,%3}, {%4,%5,%6,%7}, {%8,%9}, {%0,%1,%2,%3};"
                 : "+f"(c[0]), "+f"(c[1]), "+f"(c[2]), "+f"(c[3])
                 : "r"(a[0]), "r"(a[1]), "r"(a[2]), "r"(a[3]), "r"(b[0]), "r"(b[1]));
}
__device__ __forceinline__ void mma16816hh(uint32_t* c, const uint32_t* a, const uint32_t* b) {
    asm volatile("mma.sync.aligned.m16n8k16.row.col.f16.f16.f16.f16 "
                 "{%0,%1}, {%2,%3,%4,%5}, {%6,%7}, {%0,%1};"
                 : "+r"(c[0]), "+r"(c[1])
                 : "r"(a[0]), "r"(a[1]), "r"(a[2]), "r"(a[3]), "r"(b[0]), "r"(b[1]));
}
__device__ __forceinline__ uint32_t ex2h2(__half2 s) {
    uint32_t r;
    asm("ex2.approx.f16x2 %0, %1;" : "=r"(r) : "r"(*(uint32_t*)&s));
    return r;
}

// ---------------- HMMA fp16 GEMM: C = A(MxK) @ BT(NxK)^T ---------------------
// epi bit0: +bias ; bit1: GELU ; bit3: fp16 out ; bit4: scale cols<Dq by QSCL
#define TSTR 40
#define TILE_B (128 * TSTR * 2)         // 10240 bytes per tile
template<int STAGES>
__global__ __launch_bounds__(256, 2) void tgemm_kernel(
    const __half* __restrict__ A, const __half* __restrict__ B,
    const float* __restrict__ bias,
    float* __restrict__ Cf, __half* __restrict__ C16,
    int K, int Nc, int epi)
{
    extern __shared__ __align__(128) unsigned char dsm[];
    const uint32_t stg = 2 * TILE_B;
    const uint32_t sb = smem_u32(dsm);
    const int tid = threadIdx.x;
    const int warp = tid >> 5, lane = tid & 31;
    const int wm = warp >> 1, wn = warp & 1;
    const int bm = blockIdx.y * 128, bn = blockIdx.x * 128;

    const int NCH = K >> 5;
    const int lrow = tid >> 2, lch = (tid & 3) << 3;

    float acc[2][8][4];
    #pragma unroll
    for (int i = 0; i < 2; i++)
        #pragma unroll
        for (int j = 0; j < 8; j++)
            #pragma unroll
            for (int q = 0; q < 4; q++) acc[i][j][q] = 0.f;

    auto issue = [&](int c) {
        if (c < NCH) {
            const int kc = c << 5;
            const uint32_t base = sb + (uint32_t)(c % STAGES) * stg;
            #pragma unroll
            for (int i = 0; i < 2; i++) {
                const int row = lrow + i * 64;
                const uint32_t so = (uint32_t)(row * TSTR + lch) * 2;
                cp16(base + so,          A + (size_t)(bm + row) * K + kc + lch);
                cp16(base + TILE_B + so, B + (size_t)(bn + row) * K + kc + lch);
            }
        }
        cp_commit();
    };

    #pragma unroll
    for (int p = 0; p < STAGES - 1; p++) issue(p);

    for (int c = 0; c < NCH; c++) {
        asm volatile("cp.async.wait_group %0;" :: "n"(STAGES - 2));
        __syncthreads();
        issue(c + STAGES - 1);
        const uint32_t base = sb + (uint32_t)(c % STAGES) * stg;
        #pragma unroll
        for (int ks = 0; ks < 2; ks++) {
            const uint32_t arow = (uint32_t)((wm * 32 + (lane & 15)) * TSTR
                                             + ks * 16 + ((lane >> 4) << 3)) * 2;
            const uint32_t brow = (uint32_t)((wn * 64 + ((lane >> 4) << 3) + (lane & 7)) * TSTR
                                             + ks * 16 + (((lane >> 3) & 1) << 3)) * 2;
            uint32_t aH[2][4], bH[4][4];
            #pragma unroll
            for (int mt = 0; mt < 2; mt++)
                ldm_x4(aH[mt], base + arow + (uint32_t)(mt * 16 * TSTR) * 2);
            #pragma unroll
            for (int nt4 = 0; nt4 < 4; nt4++)
                ldm_x4(bH[nt4], base + TILE_B + brow + (uint32_t)(nt4 * 16 * TSTR) * 2);
            #pragma unroll
            for (int mt = 0; mt < 2; mt++)
                #pragma unroll
                for (int nt = 0; nt < 8; nt++)
                    mma16816h(acc[mt][nt], aH[mt], &bH[nt >> 1][(nt & 1) * 2]);
        }
        __syncthreads();
    }

    #pragma unroll
    for (int mt = 0; mt < 2; mt++) {
        const int r0 = bm + wm * 32 + mt * 16 + (lane >> 2);
        #pragma unroll
        for (int nt = 0; nt < 8; nt++) {
            const int gn = bn + wn * 64 + nt * 8 + ((lane & 3) << 1);
            #pragma unroll
            for (int half = 0; half < 2; half++) {
                const int row = r0 + half * 8;
                float v0 = acc[mt][nt][half * 2 + 0];
                float v1 = acc[mt][nt][half * 2 + 1];
                if (epi & 1) { v0 += bias[gn]; v1 += bias[gn + 1]; }
                if (epi & 2) {
                    v0 = 0.5f * v0 * (1.f + erff(v0 * 0.7071067811865475f));
                    v1 = 0.5f * v1 * (1.f + erff(v1 * 0.7071067811865475f));
                }
                if ((epi & 16) && gn < Dq) { v0 *= QSCL; v1 *= QSCL; }
                const size_t idx = (size_t)row * Nc + gn;
                if (epi & 8) {
                    *(__half2*)(C16 + idx) = __floats2half2_rn(v0, v1);
                } else {
                    *(float2*)(Cf + idx) = make_float2(v0, v1);
                }
            }
        }
    }
}

// ---------------- fused flash attention (fp16 acc, half2 harmonic) -----------
#define FLASH_STAGE 37632
#define FLASH_Q     18432
#define FLASH_SMEM  (FLASH_Q + 2 * FLASH_STAGE)     // 93696
__global__ __launch_bounds__(256, 2) void flash_kernel(
    const __half* __restrict__ QKV,
    const __half* __restrict__ cph, const __half* __restrict__ sph,
    const __half* __restrict__ maskh,
    __half* __restrict__ Mh)
{
    extern __shared__ __align__(128) unsigned char fsm[];
    const int tid = threadIdx.x, warp = tid >> 5, lane = tid & 31;
    const int wq = warp & 3, wn = warp >> 2;
    const int bh = blockIdx.y, b = bh >> 3, hh = bh & 7;
    const int n0 = blockIdx.x * 128;
    const uint32_t sb = smem_u32(fsm);

    const __half* gQ = QKV + ((size_t)b * Nq + n0) * QKVS + hh * DHq;
    #pragma unroll
    for (int i = 0; i < 4; i++) {
        const int id = tid + i * 256, row = id >> 3, ch = id & 7;
        cp16(sb + row * 144 + ch * 16, gQ + (size_t)row * QKVS + ch * 8);
    }
    cp_commit();

    auto issueKV = [&](int step, int s) {
        const uint32_t ku = sb + FLASH_Q + s * FLASH_STAGE;
        const uint32_t vu = ku + 18432, cku = ku + 36864, sku = ku + 37120, mku = ku + 37376;
        const __half* gK = QKV + ((size_t)b * Nq + step * 128) * QKVS + Dq + hh * DHq;
        const __half* gV = gK + Dq;
        #pragma unroll
        for (int i = 0; i < 4; i++) {
            const int id = tid + i * 256, row = id >> 3, ch = id & 7;
            cp16(ku + row * 144 + ch * 16, gK + (size_t)row * QKVS + ch * 8);
            cp16(vu + row * 144 + ch * 16, gV + (size_t)row * QKVS + ch * 8);
        }
        if (tid < 16)      cp16(cku + tid * 16, cph + (size_t)bh * Nq + step * 128 + tid * 8);
        else if (tid < 32) cp16(sku + (tid - 16) * 16, sph + (size_t)bh * Nq + step * 128 + (tid - 16) * 8);
        else if (tid < 48) cp16(mku + (tid - 32) * 16, maskh + (size_t)b * Nq + step * 128 + (tid - 32) * 8);
        cp_commit();
    };
    issueKV(0, 0);
    issueKV(1, 1);
    cp_wait1();
    __syncthreads();

    const int qbase = wq * 32, r = lane >> 2;
    uint32_t qf[2][4][4];
    #pragma unroll
    for (int t = 0; t < 2; t++)
        #pragma unroll
        for (int kc = 0; kc < 4; kc++)
            ldm_x4(qf[t][kc], sb + (uint32_t)((qbase + t * 16 + (lane & 15)) * 144
                                              + (kc * 16 + ((lane >> 4) << 3)) * 2));
    const __half2 cqA = __half2half2(cph[(size_t)bh * Nq + n0 + qbase + r]);
    const __half2 sqA = __half2half2(sph[(size_t)bh * Nq + n0 + qbase + r]);
    const __half2 cqB = __half2half2(cph[(size_t)bh * Nq + n0 + qbase + r + 8]);
    const __half2 sqB = __half2half2(sph[(size_t)bh * Nq + n0 + qbase + r + 8]);
    const __half2 cqC = __half2half2(cph[(size_t)bh * Nq + n0 + qbase + 16 + r]);
    const __half2 sqC = __half2half2(sph[(size_t)bh * Nq + n0 + qbase + 16 + r]);
    const __half2 cqD = __half2half2(cph[(size_t)bh * Nq + n0 + qbase + 16 + r + 8]);
    const __half2 sqD = __half2half2(sph[(size_t)bh * Nq + n0 + qbase + 16 + r + 8]);

    uint32_t O[2][8][2];
    #pragma unroll
    for (int t = 0; t < 2; t++)
        #pragma unroll
        for (int i = 0; i < 8; i++) { O[t][i][0] = 0u; O[t][i][1] = 0u; }
    float l[4] = {0.f, 0.f, 0.f, 0.f};

    const int NSTEP = Nq / 128;
    for (int c = 0; c < NSTEP; c++) {
        if (c > 0) { cp_wait1(); __syncthreads(); }
        const uint32_t ku = sb + FLASH_Q + (c & 1) * FLASH_STAGE;
        const uint32_t vu = ku + 18432;
        const __half* ckh = (const __half*)(fsm + FLASH_Q + (c & 1) * FLASH_STAGE + 36864);
        const __half* skh = ckh + 128;
        const __half* mkh = skh + 128;

        uint32_t c0[8][2], c1[8][2];
        #pragma unroll
        for (int g = 0; g < 8; g++) {
            c0[g][0] = 0u; c0[g][1] = 0u; c1[g][0] = 0u; c1[g][1] = 0u;
        }

        #pragma unroll
        for (int kc = 0; kc < 4; kc++) {
            #pragma unroll
            for (int gp = 0; gp < 4; gp++) {
                uint32_t bb[4];
                const int krow = wn * 64 + gp * 16 + ((lane >> 4) << 3) + (lane & 7);
                ldm_x4(bb, ku + (uint32_t)(krow * 144 + (kc * 16 + (((lane >> 3) & 1) << 3)) * 2));
                mma16816hh(c0[2 * gp],     qf[0][kc], bb);
                mma16816hh(c0[2 * gp + 1], qf[0][kc], bb + 2);
                mma16816hh(c1[2 * gp],     qf[1][kc], bb);
                mma16816hh(c1[2 * gp + 1], qf[1][kc], bb + 2);
            }
        }

        __half2 L0 = __floats2half2_rn(0.f, 0.f), L1 = L0, L2 = L0, L3 = L0;
        #pragma unroll
        for (int g = 0; g < 8; g++) {
            const int kg = wn * 64 + g * 8 + ((lane & 3) << 1);
            const __half2 ck2 = *(const __half2*)(ckh + kg);
            const __half2 sk2 = *(const __half2*)(skh + kg);
            const __half2 mk2 = *(const __half2*)(mkh + kg);
            {
                const __half2 cv = *(__half2*)&c0[g][0];
                const __half2 hx = __hfma2(sqA, sk2, __hmul2(cqA, ck2));
                const uint32_t p = ex2h2(__hadd2(__hfma2(cv, hx, cv), mk2));
                c0[g][0] = p;
                L0 = __hadd2(L0, *(__half2*)&p);
            }
            {
                const __half2 cv = *(__half2*)&c0[g][1];
                const __half2 hx = __hfma2(sqB, sk2, __hmul2(cqB, ck2));
                const uint32_t p = ex2h2(__hadd2(__hfma2(cv, hx, cv), mk2));
                c0[g][1] = p;
                L1 = __hadd2(L1, *(__half2*)&p);
            }
            {
                const __half2 cv = *(__half2*)&c1[g][0];
                const __half2 hx = __hfma2(sqC, sk2, __hmul2(cqC, ck2));
                const uint32_t p = ex2h2(__hadd2(__hfma2(cv, hx, cv), mk2));
                c1[g][0] = p;
                L2 = __hadd2(L2, *(__half2*)&p);
            }
            {
                const __half2 cv = *(__half2*)&c1[g][1];
                const __half2 hx = __hfma2(sqD, sk2, __hmul2(cqD, ck2));
                const uint32_t p = ex2h2(__hadd2(__hfma2(cv, hx, cv), mk2));
                c1[g][1] = p;
                L3 = __hadd2(L3, *(__half2*)&p);
            }
        }
        l[0] += __low2float(L0) + __high2float(L0);
        l[1] += __low2float(L1) + __high2float(L1);
        l[2] += __low2float(L2) + __high2float(L2);
        l[3] += __low2float(L3) + __high2float(L3);

        #pragma unroll
        for (int kc2 = 0; kc2 < 4; kc2++) {
            uint32_t aA[4], aB[4];
            aA[0] = c0[2 * kc2][0];     aA[1] = c0[2 * kc2][1];
            aA[2] = c0[2 * kc2 + 1][0]; aA[3] = c0[2 * kc2 + 1][1];
            aB[0] = c1[2 * kc2][0];     aB[1] = c1[2 * kc2][1];
            aB[2] = c1[2 * kc2 + 1][0]; aB[3] = c1[2 * kc2 + 1][1];
            const int vrow = wn * 64 + kc2 * 16 + (lane & 15);
            #pragma unroll
            for (int dgp = 0; dgp < 4; dgp++) {
                uint32_t bb[4];
                ldm_x4_t(bb, vu + (uint32_t)(vrow * 144 + (dgp * 16 + ((lane >> 4) << 3)) * 2));
                mma16816hh(O[0][2 * dgp],     aA, bb);
                mma16816hh(O[0][2 * dgp + 1], aA, bb + 2);
                mma16816hh(O[1][2 * dgp],     aB, bb);
                mma16816hh(O[1][2 * dgp + 1], aB, bb + 2);
            }
        }
        __syncthreads();
        if (c + 2 < NSTEP) issueKV(c + 2, c & 1);
    }

    #pragma unroll
    for (int i = 0; i < 4; i++) {
        l[i] += __shfl_xor_sync(~0u, l[i], 1);
        l[i] += __shfl_xor_sync(~0u, l[i], 2);
    }

    float* redO = (float*)fsm;                       // [128][66]
    float* redL = (float*)(fsm + 128 * 66 * 4);      // [128]
    if (wn == 1) {
        #pragma unroll
        for (int t = 0; t < 2; t++) {
            const int row0 = qbase + t * 16 + r, row1 = row0 + 8;
            #pragma unroll
            for (int dg = 0; dg < 8; dg++) {
                const int col = dg * 8 + ((lane & 3) << 1);
                const float2 a0 = __half22float2(*(__half2*)&O[t][dg][0]);
                const float2 a1 = __half22float2(*(__half2*)&O[t][dg][1]);
                redO[row0 * 66 + col]     = a0.x;
                redO[row0 * 66 + col + 1] = a0.y;
                redO[row1 * 66 + col]     = a1.x;
                redO[row1 * 66 + col + 1] = a1.y;
            }
            if ((lane & 3) == 0) { redL[row0] = l[2 * t]; redL[row1] = l[2 * t + 1]; }
        }
    }
    __syncthreads();
    if (wn == 0) {
        #pragma unroll
        for (int t = 0; t < 2; t++) {
            const int row0 = qbase + t * 16 + r, row1 = row0 + 8;
            const float i0 = 1.f / (l[2 * t] + redL[row0]);
            const float i1 = 1.f / (l[2 * t + 1] + redL[row1]);
            const size_t gr0 = (size_t)(b * Nq + n0 + row0) * Dq + hh * DHq;
            const size_t gr1 = (size_t)(b * Nq + n0 + row1) * Dq + hh * DHq;
            #pragma unroll
            for (int dg = 0; dg < 8; dg++) {
                const int col = dg * 8 + ((lane & 3) << 1);
                const float2 a0 = __half22float2(*(__half2*)&O[t][dg][0]);
                const float2 a1 = __half22float2(*(__half2*)&O[t][dg][1]);
                *(__half2*)(Mh + gr0 + col) =
                    __floats2half2_rn((a0.x + redO[row0 * 66 + col]) * i0,
                                      (a0.y + redO[row0 * 66 + col + 1]) * i0);
                *(__half2*)(Mh + gr1 + col) =
                    __floats2half2_rn((a1.x + redO[row1 * 66 + col]) * i1,
                                      (a1.y + redO[row1 * 66 + col + 1]) * i1);
            }
        }
    }
}

// ---------------- weight transpose helpers -----------------------------------
__device__ __forceinline__ void wtile_h(const float* __restrict__ W, __half* __restrict__ T,
                                        int K, int Nc, int k0, int n0, int tx, int ty,
                                        float t[32][33]) {
    #pragma unroll
    for (int i = ty; i < 32; i += 8) t[i][tx] = W[(size_t)(k0 + i) * Nc + n0 + tx];
    __syncthreads();
    #pragma unroll
    for (int i = ty; i < 32; i += 8)
        T[(size_t)(n0 + i) * K + k0 + tx] = __float2half_rn(t[tx][i]);
}

// part A: Wq/Wk/Wv transpose + h->fp16 + mask (prereqs of QKV GEMM + flash)
__global__ void wtransA_kernel(
    const float* Wq, const float* Wk, const float* Wv, const float* h,
    const unsigned char* mask,
    __half* qkvT, __half* h16, __half* maskh)
{
    __shared__ float t[32][33];
    const int tx = threadIdx.x, ty = threadIdx.y;
    const int tid = ty * 32 + tx;
    int id = blockIdx.x;
    if (id < 768) {
        const int w = id >> 8, tl = id & 255;
        const int n0 = (tl & 15) * 32, k0 = (tl >> 4) * 32;
        const float* W = (w == 0) ? Wq : (w == 1) ? Wk : Wv;
        wtile_h(W, qkvT + (size_t)w * Dq * Dq, Dq, Dq, k0, n0, tx, ty, t);
    } else if (id < 1280) {
        const size_t base = (size_t)(id - 768) * 4096 + tid * 16;
        #pragma unroll
        for (int i = 0; i < 4; i++) {
            const float4 v = *(const float4*)(h + base + i * 4);
            *(__half2*)(h16 + base + i * 4)     = __floats2half2_rn(v.x, v.y);
            *(__half2*)(h16 + base + i * 4 + 2) = __floats2half2_rn(v.z, v.w);
        }
    } else {
        for (int i = tid; i < Bq * Nq; i += 256)
            maskh[i] = __float2half(mask[i] ? -100.f : 0.f);
    }
}

// part B: Wo/W1/W2 transpose (side stream; needed only after flash)
__global__ void wtransB_kernel(
    const float* Wo, const float* W1, const float* W2,
    __half* oT, __half* w1T, __half* w2T)
{
    __shared__ float t[32][33];
    const int tx = threadIdx.x, ty = threadIdx.y;
    int id = blockIdx.x;
    if (id < 256) {
        const int n0 = (id & 15) * 32, k0 = (id >> 4) * 32;
        wtile_h(Wo, oT, Dq, Dq, k0, n0, tx, ty, t);
    } else if (id < 1280) {
        const int tl = id - 256;
        wtile_h(W1, w1T, Dq, Fq, (tl >> 6) * 32, (tl & 63) * 32, tx, ty, t);
    } else {
        const int tl = id - 1280;
        wtile_h(W2, w2T, Fq, Dq, (tl >> 4) * 32, (tl & 15) * 32, tx, ty, t);
    }
}

// ---------------- 8-wide projection: cos/sin (mode0) / phases+delta (mode1) --
__global__ __launch_bounds__(256) void proj8_kernel(
    const float* __restrict__ X, const float* __restrict__ W8,
    const float* __restrict__ b8, const float* __restrict__ phases,
    float* __restrict__ out, __half* __restrict__ cph, __half* __restrict__ sph,
    const float* __restrict__ rn, float* __restrict__ out_delta, int mode)
{
    if (mode && blockIdx.x == ROWS / 32) {
        __shared__ float red[256];
        const int tid = threadIdx.x;
        float s = 0.f;
        for (int i = tid; i < ROWS; i += 256) s += rn[i];
        red[tid] = s; __syncthreads();
        #pragma unroll
        for (int o = 128; o; o >>= 1) { if (tid < o) red[tid] += red[tid + o]; __syncthreads(); }
        if (tid == 0) out_delta[0] = red[0] * (1.f / ROWS);
        return;
    }
    __shared__ float w8t[8][516];
    __shared__ float b8s[8];
    const int tid = threadIdx.x;
    for (int i = tid; i < Dq * Hq; i += 256) w8t[i & 7][i >> 3] = W8[i];
    if (tid < 8) b8s[tid] = b8[tid];
    __syncthreads();
    const int warp = tid >> 5, lane = tid & 31;
    #pragma unroll
    for (int rr = 0; rr < 4; rr++) {
        const int row = blockIdx.x * 32 + warp * 4 + rr;
        const float4* X4 = (const float4*)(X + (size_t)row * Dq);
        float acc[8] = {0.f, 0.f, 0.f, 0.f, 0.f, 0.f, 0.f, 0.f};
        #pragma unroll
        for (int i = 0; i < 4; i++) {
            const int c4 = lane + i * 32;
            const float4 xv = X4[c4];
            #pragma unroll
            for (int w = 0; w < 8; w++) {
                const float4 wv = ((const float4*)&w8t[w][0])[c4];
                acc[w] += xv.x * wv.x + xv.y * wv.y + xv.z * wv.z + xv.w * wv.w;
            }
        }
        #pragma unroll
        for (int w = 0; w < 8; w++)
            #pragma unroll
            for (int o = 16; o; o >>= 1) acc[w] += __shfl_xor_sync(~0u, acc[w], o);
        if (lane < 8) {
            float s = b8s[lane];
            #pragma unroll
            for (int w = 0; w < 8; w++) if (lane == w) s += acc[w];
            if (mode) {
                out[(size_t)row * Hq + lane] = phases[(size_t)row * Hq + lane]
                                               + 0.31415926535897932f * tanhf(s);
            } else {
                const int b = row >> 11, n = row & 2047;
                cph[(size_t)(b * Hq + lane) * Nq + n] = __float2half(cosf(s));
                sph[(size_t)(b * Hq + lane) * Nq + n] = __float2half(sinf(s));
            }
        }
    }
}

// ---------------- residual add + LayerNorm (warp per row) --------------------
__global__ __launch_bounds__(256) void addln_kernel(
    const float* __restrict__ X, const float* __restrict__ Y,
    const float* __restrict__ g, const float* __restrict__ be,
    float* __restrict__ out, __half* __restrict__ oh16,
    const float* __restrict__ href, float* __restrict__ rn)
{
    const int warp = threadIdx.x >> 5, lane = threadIdx.x & 31;
    const size_t row = blockIdx.x * 8 + warp;
    const float4* X4 = (const float4*)(X + row * Dq);
    const float4* Y4 = (const float4*)(Y + row * Dq);
    float a[16];
    float s = 0.f;
    #pragma unroll
    for (int i = 0; i < 4; i++) {
        const float4 xv = X4[lane + i * 32];
        const float4 yv = Y4[lane + i * 32];
        a[4 * i + 0] = xv.x + yv.x; a[4 * i + 1] = xv.y + yv.y;
        a[4 * i + 2] = xv.z + yv.z; a[4 * i + 3] = xv.w + yv.w;
        s += a[4 * i] + a[4 * i + 1] + a[4 * i + 2] + a[4 * i + 3];
    }
    #pragma unroll
    for (int o = 16; o; o >>= 1) s += __shfl_xor_sync(~0u, s, o);
    const float mu = s * (1.f / Dq);
    float vs = 0.f;
    #pragma unroll
    for (int i = 0; i < 16; i++) { const float d = a[i] - mu; vs += d * d; }
    #pragma unroll
    for (int o = 16; o; o >>= 1) vs += __shfl_xor_sync(~0u, vs, o);
    const float rstd = rsqrtf(vs * (1.f / Dq) + 1e-5f);
    float ss = 0.f;
    #pragma unroll
    for (int i = 0; i < 4; i++) {
        const int c4 = lane + i * 32;
        const float4 gv = ((const float4*)g)[c4];
        const float4 bv = ((const float4*)be)[c4];
        float4 r;
        r.x = (a[4 * i + 0] - mu) * rstd * gv.x + bv.x;
        r.y = (a[4 * i + 1] - mu) * rstd * gv.y + bv.y;
        r.z = (a[4 * i + 2] - mu) * rstd * gv.z + bv.z;
        r.w = (a[4 * i + 3] - mu) * rstd * gv.w + bv.w;
        ((float4*)(out + row * Dq))[c4] = r;
        if (oh16) {
            *(__half2*)(oh16 + row * Dq + c4 * 4)     = __floats2half2_rn(r.x, r.y);
            *(__half2*)(oh16 + row * Dq + c4 * 4 + 2) = __floats2half2_rn(r.z, r.w);
        }
        if (href) {
            const float4 hv = ((const float4*)(href + row * Dq))[c4];
            const float d0 = r.x - hv.x, d1 = r.y - hv.y, d2 = r.z - hv.z, d3 = r.w - hv.w;
            ss += d0 * d0 + d1 * d1 + d2 * d2 + d3 * d3;
        }
    }
    if (href) {
        #pragma unroll
        for (int o = 16; o; o >>= 1) ss += __shfl_xor_sync(~0u, ss, o);
        if (lane == 0) rn[row] = sqrtf(ss);
    }
}

// ---------------- launch ------------------------------------------------------
extern "C" void kernel_launch(void* const* d_in, const int* in_sizes, int n_in,
                              void* d_out, int out_size) {
    const float* h      = (const float*)d_in[0];
    const float* phases = (const float*)d_in[1];
    const unsigned char* mask = (const unsigned char*)d_in[2];
    const float* Wq  = (const float*)d_in[3];
    const float* Wk  = (const float*)d_in[4];
    const float* Wp  = (const float*)d_in[5];
    const float* bp  = (const float*)d_in[6];
    const float* Wv  = (const float*)d_in[7];
    const float* Wo  = (const float*)d_in[8];
    const float* W1  = (const float*)d_in[9];
    const float* b1  = (const float*)d_in[10];
    const float* W2  = (const float*)d_in[11];
    const float* b2  = (const float*)d_in[12];
    const float* g1  = (const float*)d_in[13];
    const float* be1 = (const float*)d_in[14];
    const float* g2  = (const float*)d_in[15];
    const float* be2 = (const float*)d_in[16];
    const float* Wph = (const float*)d_in[17];
    const float* bph = (const float*)d_in[18];

    float* out_h2     = (float*)d_out;
    float* out_phases = out_h2 + (size_t)ROWS * Dq;
    float* out_delta  = out_phases + (size_t)ROWS * Hq;

    float *msgO, *h1, *ffn2, *rn;
    __half *QKVh, *h16, *mh, *h1h, *f1h, *WqkvT, *WoT, *W1T, *W2T, *cphh, *sphh, *maskhp;
    cudaGetSymbolAddress((void**)&msgO, g_msgO);
    cudaGetSymbolAddress((void**)&h1, g_h1);    cudaGetSymbolAddress((void**)&ffn2, g_ffn2);
    cudaGetSymbolAddress((void**)&rn, g_rn);
    cudaGetSymbolAddress((void**)&QKVh, g_QKVh);
    cudaGetSymbolAddress((void**)&h16, g_h16);
    cudaGetSymbolAddress((void**)&mh, g_mh);
    cudaGetSymbolAddress((void**)&h1h, g_h1h);
    cudaGetSymbolAddress((void**)&f1h, g_ffn1h);
    cudaGetSymbolAddress((void**)&WqkvT, g_WqkvT);
    cudaGetSymbolAddress((void**)&WoT, g_WoT);
    cudaGetSymbolAddress((void**)&W1T, g_W1T);
    cudaGetSymbolAddress((void**)&W2T, g_W2T);
    cudaGetSymbolAddress((void**)&cphh, g_cph16);
    cudaGetSymbolAddress((void**)&sphh, g_sph16);
    cudaGetSymbolAddress((void**)&maskhp, g_mask16);

    // side stream + events (created once, on the non-captured correctness call)
    static cudaStream_t s2 = nullptr;
    static cudaEvent_t evStart = nullptr, evP = nullptr, evB = nullptr;
    if (!s2) {
        cudaStreamCreateWithFlags(&s2, cudaStreamNonBlocking);
        cudaEventCreateWithFlags(&evStart, cudaEventDisableTiming);
        cudaEventCreateWithFlags(&evP, cudaEventDisableTiming);
        cudaEventCreateWithFlags(&evB, cudaEventDisableTiming);
    }

    const int smG = 4 * 2 * TILE_B;           // 81920
    cudaFuncSetAttribute(flash_kernel, cudaFuncAttributeMaxDynamicSharedMemorySize, FLASH_SMEM);
    cudaFuncSetAttribute((const void*)tgemm_kernel<4>, cudaFuncAttributeMaxDynamicSharedMemorySize, smG);

    const dim3 tb(32, 8);

    // fork: side stream does phase cos/sin + Wo/W1/W2 transpose
    cudaEventRecord(evStart, 0);
    cudaStreamWaitEvent(s2, evStart, 0);
    proj8_kernel<<<ROWS / 32, 256, 0, s2>>>(h, Wp, bp, nullptr, nullptr, cphh, sphh,
                                            nullptr, nullptr, 0);
    cudaEventRecord(evP, s2);
    wtransB_kernel<<<2304, tb, 0, s2>>>(Wo, W1, W2, WoT, W1T, W2T);
    cudaEventRecord(evB, s2);

    // main: QKV prereqs + GEMM
    wtransA_kernel<<<1281, tb>>>(Wq, Wk, Wv, h, mask, WqkvT, h16, maskhp);
    tgemm_kernel<4><<<dim3(QKVS / 128, ROWS / 128), 256, smG>>>(
        h16, WqkvT, nullptr, nullptr, QKVh, Dq, QKVS, 8 | 16);

    // flash (needs cos/sin from side stream)
    cudaStreamWaitEvent(0, evP, 0);
    flash_kernel<<<dim3(Nq / 128, BHq), 256, FLASH_SMEM>>>(QKVh, cphh, sphh, maskhp, mh);

    // Wo projection (needs WoT from side stream; joins the fork)
    cudaStreamWaitEvent(0, evB, 0);
    tgemm_kernel<4><<<dim3(Dq / 128, ROWS / 128), 256, smG>>>(
        mh, WoT, nullptr, msgO, nullptr, Dq, Dq, 0);
    addln_kernel<<<ROWS / 8, 256>>>(h, msgO, g1, be1, h1, h1h, nullptr, nullptr);

    // FFN (fp16)
    tgemm_kernel<4><<<dim3(Fq / 128, ROWS / 128), 256, smG>>>(
        h1h, W1T, b1, nullptr, f1h, Dq, Fq, 11);
    tgemm_kernel<4><<<dim3(Dq / 128, ROWS / 128), 256, smG>>>(
        f1h, W2T, b2, ffn2, nullptr, Fq, Dq, 1);
    addln_kernel<<<ROWS / 8, 256>>>(h1, ffn2, g2, be2, out_h2, nullptr, h, rn);

    // phase update + delta (one launch)
    proj8_kernel<<<ROWS / 32 + 1, 256>>>(out_h2, Wph, bph, phases, out_phases,
                                         nullptr, nullptr, rn, out_delta, 1);
}

// round 16
// speedup vs baseline: 1.2764x; 1.0635x over previous
#include <cuda_runtime.h>
#include <cuda_bf16.h>
#include <cuda_fp16.h>
#include <math.h>
#include <stdint.h>

#define Bq 2
#define Nq 2048
#define Dq 512
#define Hq 8
#define Fq 2048
#define DHq 64
#define ROWS (Bq*Nq)            // 4096
#define BHq (Bq*Hq)             // 16
#define QKVS (3*Dq)             // 1536
#define QSCL 0.0901684403f      // (1/16) * log2(e)

// ---------------- scratch (static device globals) ---------------------------
__device__ float g_msgO[ROWS*Dq];
__device__ float g_h1[ROWS*Dq];
__device__ float g_ffn2[ROWS*Dq];
__device__ float g_rn[ROWS];

__device__ __half g_QKVh[(size_t)ROWS*QKVS];
__device__ __half g_h16[ROWS*Dq];
__device__ __half g_mh[ROWS*Dq];
__device__ __half g_h1h[ROWS*Dq];
__device__ __half g_ffn1h[(size_t)ROWS*Fq];
__device__ __half g_WqkvT[3*Dq*Dq];
__device__ __half g_WoT[Dq*Dq];
__device__ __half g_W1T[(size_t)Fq*Dq];
__device__ __half g_W2T[(size_t)Dq*Fq];
__device__ __half g_cph16[BHq*Nq];
__device__ __half g_sph16[BHq*Nq];
__device__ __half g_mask16[Bq*Nq];

// ---------------- PTX helpers -----------------------------------------------
__device__ __forceinline__ uint32_t smem_u32(const void* p) {
    return (uint32_t)__cvta_generic_to_shared(p);
}
__device__ __forceinline__ void cp16(uint32_t s, const void* g) {
    asm volatile("cp.async.cg.shared.global [%0], [%1], 16;" :: "r"(s), "l"(g));
}
__device__ __forceinline__ void cp_commit() { asm volatile("cp.async.commit_group;" ::: "memory"); }
__device__ __forceinline__ void cp_wait1()  { asm volatile("cp.async.wait_group 1;" ::: "memory"); }

__device__ __forceinline__ void ldm_x4(uint32_t* r, uint32_t addr) {
    asm volatile("ldmatrix.sync.aligned.m8n8.x4.shared.b16 {%0,%1,%2,%3}, [%4];"
                 : "=r"(r[0]), "=r"(r[1]), "=r"(r[2]), "=r"(r[3]) : "r"(addr));
}
__device__ __forceinline__ void ldm_x4_t(uint32_t* r, uint32_t addr) {
    asm volatile("ldmatrix.sync.aligned.m8n8.x4.trans.shared.b16 {%0,%1,%2,%3}, [%4];"
                 : "=r"(r[0]), "=r"(r[1]), "=r"(r[2]), "=r"(r[3]) : "r"(addr));
}
__device__ __forceinline__ void mma16816h(float* c, const uint32_t* a, const uint32_t* b) {
    asm volatile("mma.sync.aligned.m16n8k16.row.col.f32.f16.f16.f32 "
                 "{%0,%1,%2,%3}, {%4,%5,%6,%7}, {%8,%9}, {%0,%1,%2,%3};"
                 : "+f"(c[0]), "+f"(c[1]), "+f"(c[2]), "+f"(c[3])
                 : "r"(a[0]), "r"(a[1]), "r"(a[2]), "r"(a[3]), "r"(b[0]), "r"(b[1]));
}
__device__ __forceinline__ void mma16816hh(uint32_t* c, const uint32_t* a, const uint32_t* b) {
    asm volatile("mma.sync.aligned.m16n8k16.row.col.f16.f16.f16.f16 "
                 "{%0,%1}, {%2,%3,%4,%5}, {%6,%7}, {%0,%1};"
                 : "+r"(c[0]), "+r"(c[1])
                 : "r"(a[0]), "r"(a[1]), "r"(a[2]), "r"(a[3]), "r"(b[0]), "r"(b[1]));
}
__device__ __forceinline__ uint32_t ex2h2(__half2 s) {
    uint32_t r;
    asm("ex2.approx.f16x2 %0, %1;" : "=r"(r) : "r"(*(uint32_t*)&s));
    return r;
}

// ---------------- HMMA fp16 GEMM: C = A(MxK) @ BT(NxK)^T ---------------------
// 64-wide K chunks, 3-stage cp.async pipeline, 144B smem row stride.
// epi bit0: +bias ; bit1: GELU ; bit3: fp16 out ; bit4: scale cols<Dq by QSCL
#define TSTR2 72                        // smem row stride in halves (64 + 8 pad)
#define TILE2 (128 * TSTR2 * 2)         // 18432 bytes per tile
#define GSTAGES 3
#define GSM (GSTAGES * 2 * TILE2)       // 110592
__global__ __launch_bounds__(256, 2) void tgemm_kernel(
    const __half* __restrict__ A, const __half* __restrict__ B,
    const float* __restrict__ bias,
    float* __restrict__ Cf, __half* __restrict__ C16,
    int K, int Nc, int epi)
{
    extern __shared__ __align__(128) unsigned char dsm[];
    const uint32_t stg = 2 * TILE2;
    const uint32_t sb = smem_u32(dsm);
    const int tid = threadIdx.x;
    const int warp = tid >> 5, lane = tid & 31;
    const int wm = warp >> 1, wn = warp & 1;
    const int bm = blockIdx.y * 128, bn = blockIdx.x * 128;

    const int NCH = K >> 6;             // 64-wide chunks
    const int lrow = tid >> 3, lch = tid & 7;

    float acc[2][8][4];
    #pragma unroll
    for (int i = 0; i < 2; i++)
        #pragma unroll
        for (int j = 0; j < 8; j++)
            #pragma unroll
            for (int q = 0; q < 4; q++) acc[i][j][q] = 0.f;

    auto issue = [&](int c) {
        if (c < NCH) {
            const int kc = c << 6;
            const uint32_t base = sb + (uint32_t)(c % GSTAGES) * stg;
            #pragma unroll
            for (int i = 0; i < 4; i++) {
                const int row = lrow + i * 32;
                const uint32_t so = (uint32_t)(row * TSTR2 + lch * 8) * 2;
                cp16(base + so,         A + (size_t)(bm + row) * K + kc + lch * 8);
                cp16(base + TILE2 + so, B + (size_t)(bn + row) * K + kc + lch * 8);
            }
        }
        cp_commit();
    };

    issue(0);
    issue(1);

    for (int c = 0; c < NCH; c++) {
        asm volatile("cp.async.wait_group 1;" ::: "memory");
        __syncthreads();
        issue(c + 2);
        const uint32_t base = sb + (uint32_t)(c % GSTAGES) * stg;
        #pragma unroll
        for (int ks = 0; ks < 4; ks++) {
            const uint32_t arow = (uint32_t)((wm * 32 + (lane & 15)) * TSTR2
                                             + ks * 16 + ((lane >> 4) << 3)) * 2;
            const uint32_t brow = (uint32_t)((wn * 64 + ((lane >> 4) << 3) + (lane & 7)) * TSTR2
                                             + ks * 16 + (((lane >> 3) & 1) << 3)) * 2;
            uint32_t aH[2][4], bH[4][4];
            #pragma unroll
            for (int mt = 0; mt < 2; mt++)
                ldm_x4(aH[mt], base + arow + (uint32_t)(mt * 16 * TSTR2) * 2);
            #pragma unroll
            for (int nt4 = 0; nt4 < 4; nt4++)
                ldm_x4(bH[nt4], base + TILE2 + brow + (uint32_t)(nt4 * 16 * TSTR2) * 2);
            #pragma unroll
            for (int mt = 0; mt < 2; mt++)
                #pragma unroll
                for (int nt = 0; nt < 8; nt++)
                    mma16816h(acc[mt][nt], aH[mt], &bH[nt >> 1][(nt & 1) * 2]);
        }
        __syncthreads();
    }

    #pragma unroll
    for (int mt = 0; mt < 2; mt++) {
        const int r0 = bm + wm * 32 + mt * 16 + (lane >> 2);
        #pragma unroll
        for (int nt = 0; nt < 8; nt++) {
            const int gn = bn + wn * 64 + nt * 8 + ((lane & 3) << 1);
            #pragma unroll
            for (int half = 0; half < 2; half++) {
                const int row = r0 + half * 8;
                float v0 = acc[mt][nt][half * 2 + 0];
                float v1 = acc[mt][nt][half * 2 + 1];
                if (epi & 1) { v0 += bias[gn]; v1 += bias[gn + 1]; }
                if (epi & 2) {
                    v0 = 0.5f * v0 * (1.f + erff(v0 * 0.7071067811865475f));
                    v1 = 0.5f * v1 * (1.f + erff(v1 * 0.7071067811865475f));
                }
                if ((epi & 16) && gn < Dq) { v0 *= QSCL; v1 *= QSCL; }
                const size_t idx = (size_t)row * Nc + gn;
                if (epi & 8) {
                    *(__half2*)(C16 + idx) = __floats2half2_rn(v0, v1);
                } else {
                    *(float2*)(Cf + idx) = make_float2(v0, v1);
                }
            }
        }
    }
}

// ---------------- fused flash attention (fp16 acc, half2 harmonic) -----------
#define FLASH_STAGE 37632
#define FLASH_Q     18432
#define FLASH_SMEM  (FLASH_Q + 2 * FLASH_STAGE)     // 93696
__global__ __launch_bounds__(256, 2) void flash_kernel(
    const __half* __restrict__ QKV,
    const __half* __restrict__ cph, const __half* __restrict__ sph,
    const __half* __restrict__ maskh,
    __half* __restrict__ Mh)
{
    extern __shared__ __align__(128) unsigned char fsm[];
    const int tid = threadIdx.x, warp = tid >> 5, lane = tid & 31;
    const int wq = warp & 3, wn = warp >> 2;
    const int bh = blockIdx.y, b = bh >> 3, hh = bh & 7;
    const int n0 = blockIdx.x * 128;
    const uint32_t sb = smem_u32(fsm);

    const __half* gQ = QKV + ((size_t)b * Nq + n0) * QKVS + hh * DHq;
    #pragma unroll
    for (int i = 0; i < 4; i++) {
        const int id = tid + i * 256, row = id >> 3, ch = id & 7;
        cp16(sb + row * 144 + ch * 16, gQ + (size_t)row * QKVS + ch * 8);
    }
    cp_commit();

    auto issueKV = [&](int step, int s) {
        const uint32_t ku = sb + FLASH_Q + s * FLASH_STAGE;
        const uint32_t vu = ku + 18432, cku = ku + 36864, sku = ku + 37120, mku = ku + 37376;
        const __half* gK = QKV + ((size_t)b * Nq + step * 128) * QKVS + Dq + hh * DHq;
        const __half* gV = gK + Dq;
        #pragma unroll
        for (int i = 0; i < 4; i++) {
            const int id = tid + i * 256, row = id >> 3, ch = id & 7;
            cp16(ku + row * 144 + ch * 16, gK + (size_t)row * QKVS + ch * 8);
            cp16(vu + row * 144 + ch * 16, gV + (size_t)row * QKVS + ch * 8);
        }
        if (tid < 16)      cp16(cku + tid * 16, cph + (size_t)bh * Nq + step * 128 + tid * 8);
        else if (tid < 32) cp16(sku + (tid - 16) * 16, sph + (size_t)bh * Nq + step * 128 + (tid - 16) * 8);
        else if (tid < 48) cp16(mku + (tid - 32) * 16, maskh + (size_t)b * Nq + step * 128 + (tid - 32) * 8);
        cp_commit();
    };
    issueKV(0, 0);
    issueKV(1, 1);
    cp_wait1();
    __syncthreads();

    const int qbase = wq * 32, r = lane >> 2;
    uint32_t qf[2][4][4];
    #pragma unroll
    for (int t = 0; t < 2; t++)
        #pragma unroll
        for (int kc = 0; kc < 4; kc++)
            ldm_x4(qf[t][kc], sb + (uint32_t)((qbase + t * 16 + (lane & 15)) * 144
                                              + (kc * 16 + ((lane >> 4) << 3)) * 2));
    const __half2 cqA = __half2half2(cph[(size_t)bh * Nq + n0 + qbase + r]);
    const __half2 sqA = __half2half2(sph[(size_t)bh * Nq + n0 + qbase + r]);
    const __half2 cqB = __half2half2(cph[(size_t)bh * Nq + n0 + qbase + r + 8]);
    const __half2 sqB = __half2half2(sph[(size_t)bh * Nq + n0 + qbase + r + 8]);
    const __half2 cqC = __half2half2(cph[(size_t)bh * Nq + n0 + qbase + 16 + r]);
    const __half2 sqC = __half2half2(sph[(size_t)bh * Nq + n0 + qbase + 16 + r]);
    const __half2 cqD = __half2half2(cph[(size_t)bh * Nq + n0 + qbase + 16 + r + 8]);
    const __half2 sqD = __half2half2(sph[(size_t)bh * Nq + n0 + qbase + 16 + r + 8]);

    uint32_t O[2][8][2];
    #pragma unroll
    for (int t = 0; t < 2; t++)
        #pragma unroll
        for (int i = 0; i < 8; i++) { O[t][i][0] = 0u; O[t][i][1] = 0u; }
    float l[4] = {0.f, 0.f, 0.f, 0.f};

    const int NSTEP = Nq / 128;
    for (int c = 0; c < NSTEP; c++) {
        if (c > 0) { cp_wait1(); __syncthreads(); }
        const uint32_t ku = sb + FLASH_Q + (c & 1) * FLASH_STAGE;
        const uint32_t vu = ku + 18432;
        const __half* ckh = (const __half*)(fsm + FLASH_Q + (c & 1) * FLASH_STAGE + 36864);
        const __half* skh = ckh + 128;
        const __half* mkh = skh + 128;

        uint32_t c0[8][2], c1[8][2];
        #pragma unroll
        for (int g = 0; g < 8; g++) {
            c0[g][0] = 0u; c0[g][1] = 0u; c1[g][0] = 0u; c1[g][1] = 0u;
        }

        #pragma unroll
        for (int kc = 0; kc < 4; kc++) {
            #pragma unroll
            for (int gp = 0; gp < 4; gp++) {
                uint32_t bb[4];
                const int krow = wn * 64 + gp * 16 + ((lane >> 4) << 3) + (lane & 7);
                ldm_x4(bb, ku + (uint32_t)(krow * 144 + (kc * 16 + (((lane >> 3) & 1) << 3)) * 2));
                mma16816hh(c0[2 * gp],     qf[0][kc], bb);
                mma16816hh(c0[2 * gp + 1], qf[0][kc], bb + 2);
                mma16816hh(c1[2 * gp],     qf[1][kc], bb);
                mma16816hh(c1[2 * gp + 1], qf[1][kc], bb + 2);
            }
        }

        __half2 L0 = __floats2half2_rn(0.f, 0.f), L1 = L0, L2 = L0, L3 = L0;
        #pragma unroll
        for (int g = 0; g < 8; g++) {
            const int kg = wn * 64 + g * 8 + ((lane & 3) << 1);
            const __half2 ck2 = *(const __half2*)(ckh + kg);
            const __half2 sk2 = *(const __half2*)(skh + kg);
            const __half2 mk2 = *(const __half2*)(mkh + kg);
            {
                const __half2 cv = *(__half2*)&c0[g][0];
                const __half2 hx = __hfma2(sqA, sk2, __hmul2(cqA, ck2));
                const uint32_t p = ex2h2(__hadd2(__hfma2(cv, hx, cv), mk2));
                c0[g][0] = p;
                L0 = __hadd2(L0, *(__half2*)&p);
            }
            {
                const __half2 cv = *(__half2*)&c0[g][1];
                const __half2 hx = __hfma2(sqB, sk2, __hmul2(cqB, ck2));
                const uint32_t p = ex2h2(__hadd2(__hfma2(cv, hx, cv), mk2));
                c0[g][1] = p;
                L1 = __hadd2(L1, *(__half2*)&p);
            }
            {
                const __half2 cv = *(__half2*)&c1[g][0];
                const __half2 hx = __hfma2(sqC, sk2, __hmul2(cqC, ck2));
                const uint32_t p = ex2h2(__hadd2(__hfma2(cv, hx, cv), mk2));
                c1[g][0] = p;
                L2 = __hadd2(L2, *(__half2*)&p);
            }
            {
                const __half2 cv = *(__half2*)&c1[g][1];
                const __half2 hx = __hfma2(sqD, sk2, __hmul2(cqD, ck2));
                const uint32_t p = ex2h2(__hadd2(__hfma2(cv, hx, cv), mk2));
                c1[g][1] = p;
                L3 = __hadd2(L3, *(__half2*)&p);
            }
        }
        l[0] += __low2float(L0) + __high2float(L0);
        l[1] += __low2float(L1) + __high2float(L1);
        l[2] += __low2float(L2) + __high2float(L2);
        l[3] += __low2float(L3) + __high2float(L3);

        #pragma unroll
        for (int kc2 = 0; kc2 < 4; kc2++) {
            uint32_t aA[4], aB[4];
            aA[0] = c0[2 * kc2][0];     aA[1] = c0[2 * kc2][1];
            aA[2] = c0[2 * kc2 + 1][0]; aA[3] = c0[2 * kc2 + 1][1];
            aB[0] = c1[2 * kc2][0];     aB[1] = c1[2 * kc2][1];
            aB[2] = c1[2 * kc2 + 1][0]; aB[3] = c1[2 * kc2 + 1][1];
            const int vrow = wn * 64 + kc2 * 16 + (lane & 15);
            #pragma unroll
            for (int dgp = 0; dgp < 4; dgp++) {
                uint32_t bb[4];
                ldm_x4_t(bb, vu + (uint32_t)(vrow * 144 + (dgp * 16 + ((lane >> 4) << 3)) * 2));
                mma16816hh(O[0][2 * dgp],     aA, bb);
                mma16816hh(O[0][2 * dgp + 1], aA, bb + 2);
                mma16816hh(O[1][2 * dgp],     aB, bb);
                mma16816hh(O[1][2 * dgp + 1], aB, bb + 2);
            }
        }
        __syncthreads();
        if (c + 2 < NSTEP) issueKV(c + 2, c & 1);
    }

    #pragma unroll
    for (int i = 0; i < 4; i++) {
        l[i] += __shfl_xor_sync(~0u, l[i], 1);
        l[i] += __shfl_xor_sync(~0u, l[i], 2);
    }

    float* redO = (float*)fsm;                       // [128][66]
    float* redL = (float*)(fsm + 128 * 66 * 4);      // [128]
    if (wn == 1) {
        #pragma unroll
        for (int t = 0; t < 2; t++) {
            const int row0 = qbase + t * 16 + r, row1 = row0 + 8;
            #pragma unroll
            for (int dg = 0; dg < 8; dg++) {
                const int col = dg * 8 + ((lane & 3) << 1);
                const float2 a0 = __half22float2(*(__half2*)&O[t][dg][0]);
                const float2 a1 = __half22float2(*(__half2*)&O[t][dg][1]);
                redO[row0 * 66 + col]     = a0.x;
                redO[row0 * 66 + col + 1] = a0.y;
                redO[row1 * 66 + col]     = a1.x;
                redO[row1 * 66 + col + 1] = a1.y;
            }
            if ((lane & 3) == 0) { redL[row0] = l[2 * t]; redL[row1] = l[2 * t + 1]; }
        }
    }
    __syncthreads();
    if (wn == 0) {
        #pragma unroll
        for (int t = 0; t < 2; t++) {
            const int row0 = qbase + t * 16 + r, row1 = row0 + 8;
            const float i0 = 1.f / (l[2 * t] + redL[row0]);
            const float i1 = 1.f / (l[2 * t + 1] + redL[row1]);
            const size_t gr0 = (size_t)(b * Nq + n0 + row0) * Dq + hh * DHq;
            const size_t gr1 = (size_t)(b * Nq + n0 + row1) * Dq + hh * DHq;
            #pragma unroll
            for (int dg = 0; dg < 8; dg++) {
                const int col = dg * 8 + ((lane & 3) << 1);
                const float2 a0 = __half22float2(*(__half2*)&O[t][dg][0]);
                const float2 a1 = __half22float2(*(__half2*)&O[t][dg][1]);
                *(__half2*)(Mh + gr0 + col) =
                    __floats2half2_rn((a0.x + redO[row0 * 66 + col]) * i0,
                                      (a0.y + redO[row0 * 66 + col + 1]) * i0);
                *(__half2*)(Mh + gr1 + col) =
                    __floats2half2_rn((a1.x + redO[row1 * 66 + col]) * i1,
                                      (a1.y + redO[row1 * 66 + col + 1]) * i1);
            }
        }
    }
}

// ---------------- weight transpose helpers -----------------------------------
__device__ __forceinline__ void wtile_h(const float* __restrict__ W, __half* __restrict__ T,
                                        int K, int Nc, int k0, int n0, int tx, int ty,
                                        float t[32][33]) {
    #pragma unroll
    for (int i = ty; i < 32; i += 8) t[i][tx] = W[(size_t)(k0 + i) * Nc + n0 + tx];
    __syncthreads();
    #pragma unroll
    for (int i = ty; i < 32; i += 8)
        T[(size_t)(n0 + i) * K + k0 + tx] = __float2half_rn(t[tx][i]);
}

// part A: Wq/Wk/Wv transpose + h->fp16 + mask (prereqs of QKV GEMM + flash)
__global__ void wtransA_kernel(
    const float* Wq, const float* Wk, const float* Wv, const float* h,
    const unsigned char* mask,
    __half* qkvT, __half* h16, __half* maskh)
{
    __shared__ float t[32][33];
    const int tx = threadIdx.x, ty = threadIdx.y;
    const int tid = ty * 32 + tx;
    int id = blockIdx.x;
    if (id < 768) {
        const int w = id >> 8, tl = id & 255;
        const int n0 = (tl & 15) * 32, k0 = (tl >> 4) * 32;
        const float* W = (w == 0) ? Wq : (w == 1) ? Wk : Wv;
        wtile_h(W, qkvT + (size_t)w * Dq * Dq, Dq, Dq, k0, n0, tx, ty, t);
    } else if (id < 1280) {
        const size_t base = (size_t)(id - 768) * 4096 + tid * 16;
        #pragma unroll
        for (int i = 0; i < 4; i++) {
            const float4 v = *(const float4*)(h + base + i * 4);
            *(__half2*)(h16 + base + i * 4)     = __floats2half2_rn(v.x, v.y);
            *(__half2*)(h16 + base + i * 4 + 2) = __floats2half2_rn(v.z, v.w);
        }
    } else {
        for (int i = tid; i < Bq * Nq; i += 256)
            maskh[i] = __float2half(mask[i] ? -100.f : 0.f);
    }
}

// part B: Wo/W1/W2 transpose (side stream; needed only after flash)
__global__ void wtransB_kernel(
    const float* Wo, const float* W1, const float* W2,
    __half* oT, __half* w1T, __half* w2T)
{
    __shared__ float t[32][33];
    const int tx = threadIdx.x, ty = threadIdx.y;
    int id = blockIdx.x;
    if (id < 256) {
        const int n0 = (id & 15) * 32, k0 = (id >> 4) * 32;
        wtile_h(Wo, oT, Dq, Dq, k0, n0, tx, ty, t);
    } else if (id < 1280) {
        const int tl = id - 256;
        wtile_h(W1, w1T, Dq, Fq, (tl >> 6) * 32, (tl & 63) * 32, tx, ty, t);
    } else {
        const int tl = id - 1280;
        wtile_h(W2, w2T, Fq, Dq, (tl >> 4) * 32, (tl & 15) * 32, tx, ty, t);
    }
}

// ---------------- 8-wide projection: cos/sin (mode0) / phases+delta (mode1) --
__global__ __launch_bounds__(256) void proj8_kernel(
    const float* __restrict__ X, const float* __restrict__ W8,
    const float* __restrict__ b8, const float* __restrict__ phases,
    float* __restrict__ out, __half* __restrict__ cph, __half* __restrict__ sph,
    const float* __restrict__ rn, float* __restrict__ out_delta, int mode)
{
    if (mode && blockIdx.x == ROWS / 32) {
        __shared__ float red[256];
        const int tid = threadIdx.x;
        float s = 0.f;
        for (int i = tid; i < ROWS; i += 256) s += rn[i];
        red[tid] = s; __syncthreads();
        #pragma unroll
        for (int o = 128; o; o >>= 1) { if (tid < o) red[tid] += red[tid + o]; __syncthreads(); }
        if (tid == 0) out_delta[0] = red[0] * (1.f / ROWS);
        return;
    }
    __shared__ float w8t[8][516];
    __shared__ float b8s[8];
    const int tid = threadIdx.x;
    for (int i = tid; i < Dq * Hq; i += 256) w8t[i & 7][i >> 3] = W8[i];
    if (tid < 8) b8s[tid] = b8[tid];
    __syncthreads();
    const int warp = tid >> 5, lane = tid & 31;
    #pragma unroll
    for (int rr = 0; rr < 4; rr++) {
        const int row = blockIdx.x * 32 + warp * 4 + rr;
        const float4* X4 = (const float4*)(X + (size_t)row * Dq);
        float acc[8] = {0.f, 0.f, 0.f, 0.f, 0.f, 0.f, 0.f, 0.f};
        #pragma unroll
        for (int i = 0; i < 4; i++) {
            const int c4 = lane + i * 32;
            const float4 xv = X4[c4];
            #pragma unroll
            for (int w = 0; w < 8; w++) {
                const float4 wv = ((const float4*)&w8t[w][0])[c4];
                acc[w] += xv.x * wv.x + xv.y * wv.y + xv.z * wv.z + xv.w * wv.w;
            }
        }
        #pragma unroll
        for (int w = 0; w < 8; w++)
            #pragma unroll
            for (int o = 16; o; o >>= 1) acc[w] += __shfl_xor_sync(~0u, acc[w], o);
        if (lane < 8) {
            float s = b8s[lane];
            #pragma unroll
            for (int w = 0; w < 8; w++) if (lane == w) s += acc[w];
            if (mode) {
                out[(size_t)row * Hq + lane] = phases[(size_t)row * Hq + lane]
                                               + 0.31415926535897932f * tanhf(s);
            } else {
                const int b = row >> 11, n = row & 2047;
                cph[(size_t)(b * Hq + lane) * Nq + n] = __float2half(cosf(s));
                sph[(size_t)(b * Hq + lane) * Nq + n] = __float2half(sinf(s));
            }
        }
    }
}

// ---------------- residual add + LayerNorm (warp per row) --------------------
__global__ __launch_bounds__(256) void addln_kernel(
    const float* __restrict__ X, const float* __restrict__ Y,
    const float* __restrict__ g, const float* __restrict__ be,
    float* __restrict__ out, __half* __restrict__ oh16,
    const float* __restrict__ href, float* __restrict__ rn)
{
    const int warp = threadIdx.x >> 5, lane = threadIdx.x & 31;
    const size_t row = blockIdx.x * 8 + warp;
    const float4* X4 = (const float4*)(X + row * Dq);
    const float4* Y4 = (const float4*)(Y + row * Dq);
    float a[16];
    float s = 0.f;
    #pragma unroll
    for (int i = 0; i < 4; i++) {
        const float4 xv = X4[lane + i * 32];
        const float4 yv = Y4[lane + i * 32];
        a[4 * i + 0] = xv.x + yv.x; a[4 * i + 1] = xv.y + yv.y;
        a[4 * i + 2] = xv.z + yv.z; a[4 * i + 3] = xv.w + yv.w;
        s += a[4 * i] + a[4 * i + 1] + a[4 * i + 2] + a[4 * i + 3];
    }
    #pragma unroll
    for (int o = 16; o; o >>= 1) s += __shfl_xor_sync(~0u, s, o);
    const float mu = s * (1.f / Dq);
    float vs = 0.f;
    #pragma unroll
    for (int i = 0; i < 16; i++) { const float d = a[i] - mu; vs += d * d; }
    #pragma unroll
    for (int o = 16; o; o >>= 1) vs += __shfl_xor_sync(~0u, vs, o);
    const float rstd = rsqrtf(vs * (1.f / Dq) + 1e-5f);
    float ss = 0.f;
    #pragma unroll
    for (int i = 0; i < 4; i++) {
        const int c4 = lane + i * 32;
        const float4 gv = ((const float4*)g)[c4];
        const float4 bv = ((const float4*)be)[c4];
        float4 r;
        r.x = (a[4 * i + 0] - mu) * rstd * gv.x + bv.x;
        r.y = (a[4 * i + 1] - mu) * rstd * gv.y + bv.y;
        r.z = (a[4 * i + 2] - mu) * rstd * gv.z + bv.z;
        r.w = (a[4 * i + 3] - mu) * rstd * gv.w + bv.w;
        ((float4*)(out + row * Dq))[c4] = r;
        if (oh16) {
            *(__half2*)(oh16 + row * Dq + c4 * 4)     = __floats2half2_rn(r.x, r.y);
            *(__half2*)(oh16 + row * Dq + c4 * 4 + 2) = __floats2half2_rn(r.z, r.w);
        }
        if (href) {
            const float4 hv = ((const float4*)(href + row * Dq))[c4];
            const float d0 = r.x - hv.x, d1 = r.y - hv.y, d2 = r.z - hv.z, d3 = r.w - hv.w;
            ss += d0 * d0 + d1 * d1 + d2 * d2 + d3 * d3;
        }
    }
    if (href) {
        #pragma unroll
        for (int o = 16; o; o >>= 1) ss += __shfl_xor_sync(~0u, ss, o);
        if (lane == 0) rn[row] = sqrtf(ss);
    }
}

// ---------------- launch ------------------------------------------------------
extern "C" void kernel_launch(void* const* d_in, const int* in_sizes, int n_in,
                              void* d_out, int out_size) {
    const float* h      = (const float*)d_in[0];
    const float* phases = (const float*)d_in[1];
    const unsigned char* mask = (const unsigned char*)d_in[2];
    const float* Wq  = (const float*)d_in[3];
    const float* Wk  = (const float*)d_in[4];
    const float* Wp  = (const float*)d_in[5];
    const float* bp  = (const float*)d_in[6];
    const float* Wv  = (const float*)d_in[7];
    const float* Wo  = (const float*)d_in[8];
    const float* W1  = (const float*)d_in[9];
    const float* b1  = (const float*)d_in[10];
    const float* W2  = (const float*)d_in[11];
    const float* b2  = (const float*)d_in[12];
    const float* g1  = (const float*)d_in[13];
    const float* be1 = (const float*)d_in[14];
    const float* g2  = (const float*)d_in[15];
    const float* be2 = (const float*)d_in[16];
    const float* Wph = (const float*)d_in[17];
    const float* bph = (const float*)d_in[18];

    float* out_h2     = (float*)d_out;
    float* out_phases = out_h2 + (size_t)ROWS * Dq;
    float* out_delta  = out_phases + (size_t)ROWS * Hq;

    float *msgO, *h1, *ffn2, *rn;
    __half *QKVh, *h16, *mh, *h1h, *f1h, *WqkvT, *WoT, *W1T, *W2T, *cphh, *sphh, *maskhp;
    cudaGetSymbolAddress((void**)&msgO, g_msgO);
    cudaGetSymbolAddress((void**)&h1, g_h1);    cudaGetSymbolAddress((void**)&ffn2, g_ffn2);
    cudaGetSymbolAddress((void**)&rn, g_rn);
    cudaGetSymbolAddress((void**)&QKVh, g_QKVh);
    cudaGetSymbolAddress((void**)&h16, g_h16);
    cudaGetSymbolAddress((void**)&mh, g_mh);
    cudaGetSymbolAddress((void**)&h1h, g_h1h);
    cudaGetSymbolAddress((void**)&f1h, g_ffn1h);
    cudaGetSymbolAddress((void**)&WqkvT, g_WqkvT);
    cudaGetSymbolAddress((void**)&WoT, g_WoT);
    cudaGetSymbolAddress((void**)&W1T, g_W1T);
    cudaGetSymbolAddress((void**)&W2T, g_W2T);
    cudaGetSymbolAddress((void**)&cphh, g_cph16);
    cudaGetSymbolAddress((void**)&sphh, g_sph16);
    cudaGetSymbolAddress((void**)&maskhp, g_mask16);

    // side stream + events (created once, on the non-captured correctness call)
    static cudaStream_t s2 = nullptr;
    static cudaEvent_t evStart = nullptr, evP = nullptr, evB = nullptr;
    if (!s2) {
        cudaStreamCreateWithFlags(&s2, cudaStreamNonBlocking);
        cudaEventCreateWithFlags(&evStart, cudaEventDisableTiming);
        cudaEventCreateWithFlags(&evP, cudaEventDisableTiming);
        cudaEventCreateWithFlags(&evB, cudaEventDisableTiming);
    }

    cudaFuncSetAttribute(flash_kernel, cudaFuncAttributeMaxDynamicSharedMemorySize, FLASH_SMEM);
    cudaFuncSetAttribute(tgemm_kernel, cudaFuncAttributeMaxDynamicSharedMemorySize, GSM);

    const dim3 tb(32, 8);

    // fork: side stream does phase cos/sin + Wo/W1/W2 transpose
    cudaEventRecord(evStart, 0);
    cudaStreamWaitEvent(s2, evStart, 0);
    proj8_kernel<<<ROWS / 32, 256, 0, s2>>>(h, Wp, bp, nullptr, nullptr, cphh, sphh,
                                            nullptr, nullptr, 0);
    cudaEventRecord(evP, s2);
    wtransB_kernel<<<2304, tb, 0, s2>>>(Wo, W1, W2, WoT, W1T, W2T);
    cudaEventRecord(evB, s2);

    // main: QKV prereqs + GEMM
    wtransA_kernel<<<1281, tb>>>(Wq, Wk, Wv, h, mask, WqkvT, h16, maskhp);
    tgemm_kernel<<<dim3(QKVS / 128, ROWS / 128), 256, GSM>>>(
        h16, WqkvT, nullptr, nullptr, QKVh, Dq, QKVS, 8 | 16);

    // flash (needs cos/sin from side stream)
    cudaStreamWaitEvent(0, evP, 0);
    flash_kernel<<<dim3(Nq / 128, BHq), 256, FLASH_SMEM>>>(QKVh, cphh, sphh, maskhp, mh);

    // Wo projection (needs WoT from side stream; joins the fork)
    cudaStreamWaitEvent(0, evB, 0);
    tgemm_kernel<<<dim3(Dq / 128, ROWS / 128), 256, GSM>>>(
        mh, WoT, nullptr, msgO, nullptr, Dq, Dq, 0);
    addln_kernel<<<ROWS / 8, 256>>>(h, msgO, g1, be1, h1, h1h, nullptr, nullptr);

    // FFN (fp16)
    tgemm_kernel<<<dim3(Fq / 128, ROWS / 128), 256, GSM>>>(
        h1h, W1T, b1, nullptr, f1h, Dq, Fq, 11);
    tgemm_kernel<<<dim3(Dq / 128, ROWS / 128), 256, GSM>>>(
        f1h, W2T, b2, ffn2, nullptr, Fq, Dq, 1);
    addln_kernel<<<ROWS / 8, 256>>>(h1, ffn2, g2, be2, out_h2, nullptr, h, rn);

    // phase update + delta (one launch)
    proj8_kernel<<<ROWS / 32 + 1, 256>>>(out_h2, Wph, bph, phases, out_phases,
                                         nullptr, nullptr, rn, out_delta, 1);
}